// round 6
// baseline (speedup 1.0000x reference)
#include <cuda_runtime.h>
#include <cstdint>

#define N_NODES 100000
#define N_EDGES 800000
#define IN_DIM 128
#define HID_DIM 256
#define OUT_DIM 40

// ---------------- scratch (device globals; no allocation allowed) ----------------
__device__ int   g_is64;
__device__ int   g_eidx[2 * N_EDGES];            // decoded edge index (src | dst)
__device__ int   g_cnt[N_NODES];
__device__ int   g_rowptr[N_NODES + 1];
__device__ int   g_cursor[N_NODES];
__device__ int   g_perm[N_EDGES];
__device__ float g_agg[(size_t)N_NODES * 256];   // layer1: stride 128; layer2: stride 256
__device__ float g_h[(size_t)N_NODES * 256];

// ---------------- small helpers ----------------
__device__ __forceinline__ float4 f4add(float4 a, float4 b) {
    a.x += b.x; a.y += b.y; a.z += b.z; a.w += b.w; return a;
}
__device__ __forceinline__ float4 f4scale(float4 a, float s) {
    a.x *= s; a.y *= s; a.z *= s; a.w *= s; return a;
}

// packed fp32x2 FMA (Blackwell): d = a*b + c per 32-bit lane of the 64-bit regs
#define FMA_F32X2(d, a, b, c) \
    asm("fma.rn.f32x2 %0, %1, %2, %3;" : "=l"(d) : "l"(a), "l"(b), "l"(c))

__device__ __forceinline__ float2 unpack_f32x2(unsigned long long v) {
    float2 r;
    asm("mov.b64 {%0, %1}, %2;" : "=f"(r.x), "=f"(r.y) : "l"(v));
    return r;
}

// ---------------- edge-index dtype probe + decode ----------------
__global__ void k_probe(const int* __restrict__ buf) {
    __shared__ int ok;
    if (threadIdx.x == 0) ok = 1;
    __syncthreads();
    int i = threadIdx.x;                 // 512 threads, pairs 0..511
    int lo = buf[2 * i];
    int hi = buf[2 * i + 1];
    if (!(hi == 0 && lo >= 0 && lo < N_NODES)) atomicAnd(&ok, 0);
    __syncthreads();
    if (threadIdx.x == 0) g_is64 = ok;
}

__global__ void k_decode(const void* __restrict__ buf) {
    int e = blockIdx.x * blockDim.x + threadIdx.x;
    if (e >= 2 * N_EDGES) return;
    int v;
    if (g_is64) v = (int)((const long long*)buf)[e];
    else        v = ((const int*)buf)[e];
    v = v < 0 ? 0 : (v >= N_NODES ? N_NODES - 1 : v);
    g_eidx[e] = v;
}

// ---------------- CSR construction ----------------
__global__ void k_zero_cnt() {
    int i = blockIdx.x * blockDim.x + threadIdx.x;
    if (i < N_NODES) g_cnt[i] = 0;
}

__global__ void k_hist() {
    int e = blockIdx.x * blockDim.x + threadIdx.x;
    if (e < N_EDGES) {
        int d = g_eidx[N_EDGES + e];
        atomicAdd(&g_cnt[d], 1);
    }
}

__global__ void k_scan() {
    const int T = 1024;
    const int CH = (N_NODES + T - 1) / T;
    int t = threadIdx.x;
    int beg = t * CH;
    int end = beg + CH; if (end > N_NODES) end = N_NODES;
    int s = 0;
    for (int i = beg; i < end; i++) s += g_cnt[i];

    __shared__ int ps[T];
    ps[t] = s;
    __syncthreads();
    for (int off = 1; off < T; off <<= 1) {
        int v = 0;
        if (t >= off) v = ps[t - off];
        __syncthreads();
        ps[t] += v;
        __syncthreads();
    }
    int run = ps[t] - s;
    for (int i = beg; i < end; i++) {
        g_rowptr[i] = run;
        g_cursor[i] = run;
        run += g_cnt[i];
    }
    if (t == 0) g_rowptr[N_NODES] = N_EDGES;
}

__global__ void k_scatter() {
    int e = blockIdx.x * blockDim.x + threadIdx.x;
    if (e < N_EDGES) {
        int s = g_eidx[e];
        int d = g_eidx[N_EDGES + e];
        int pos = atomicAdd(&g_cursor[d], 1);
        g_perm[pos] = s;
    }
}

// ---------------- mean aggregation: one warp per node, no atomics ----------------
template <int D>
__global__ void __launch_bounds__(256) k_agg(const float* __restrict__ feat,
                                             float* __restrict__ out) {
    int warp = (blockIdx.x * blockDim.x + threadIdx.x) >> 5;
    if (warp >= N_NODES) return;
    int lane = threadIdx.x & 31;

    int beg = g_rowptr[warp];
    int end = g_rowptr[warp + 1];

    float4 a0 = make_float4(0.f, 0.f, 0.f, 0.f);
    float4 a1 = make_float4(0.f, 0.f, 0.f, 0.f);
    for (int e = beg; e < end; e++) {
        int s = g_perm[e];
        const float4* row = (const float4*)(feat + (size_t)s * D);
        a0 = f4add(a0, row[lane]);
        if (D == 256) a1 = f4add(a1, row[lane + 32]);
    }
    int deg = end - beg;
    float inv = 1.0f / (float)(deg > 0 ? deg : 1);
    float4* o = (float4*)(out + (size_t)warp * D);
    o[lane] = f4scale(a0, inv);
    if (D == 256) o[lane + 32] = f4scale(a1, inv);
}

// ---------------- fused SAGE GEMM (FFMA2):  C = op( Aagg@Wl + b + Ax@Wr ) ----------------
// A tiles stored TRANSPOSED in smem (rows packed in pairs for f32x2),
// W tiles stored DUPLICATED ((w,w) pairs) so every FFMA2 operand comes
// straight from an LDS with zero packing instructions.
template <int K, int NTOT, bool RELU>
__global__ void __launch_bounds__(256) k_gemm(const float* __restrict__ Aagg,
                                              const float* __restrict__ Ax,
                                              const float* __restrict__ Wl,
                                              const float* __restrict__ Wr,
                                              const float* __restrict__ bias,
                                              float* __restrict__ C) {
    constexpr int BM = 64, NC = 64, KB = 16;
    __shared__ __align__(16) float sAgT[KB][BM + 4];   // [k][row], pitch 272B (16B aligned)
    __shared__ __align__(16) float sAxT[KB][BM + 4];
    __shared__ __align__(16) float sWl2[KB][2 * NC];   // duplicated: [k][2n]=[k][2n+1]=w
    __shared__ __align__(16) float sWr2[KB][2 * NC];

    int tid = threadIdx.x;
    int mBase = blockIdx.x * BM;
    int tx = tid & 15, ty = tid >> 4;
    int r0 = ty * 4;                  // 4 rows = 2 f32x2 pairs
    int c0 = tx * 4;                  // 4 cols
    int lr = tid >> 2, lc = tid & 3;  // A loader: 64 rows x 4 float4-cols
    int wn = tid & 63, wk = tid >> 6; // W loader: col wn, k rows wk*4 + i

    for (int ncb = 0; ncb < NTOT; ncb += NC) {
        unsigned long long acc[2][4];   // [row-pair][col], f32x2 packed
        #pragma unroll
        for (int p = 0; p < 2; p++)
            #pragma unroll
            for (int j = 0; j < 4; j++) acc[p][j] = 0ULL;

        for (int kb = 0; kb < K; kb += KB) {
            // --- A tiles: global float4 read, transposed scalar smem stores ---
            {
                int m = mBase + lr;
                float4 va = make_float4(0.f, 0.f, 0.f, 0.f);
                float4 vx = va;
                if (m < N_NODES) {
                    va = *(const float4*)(Aagg + (size_t)m * K + kb + lc * 4);
                    vx = *(const float4*)(Ax   + (size_t)m * K + kb + lc * 4);
                }
                int k4 = lc * 4;
                sAgT[k4 + 0][lr] = va.x;
                sAgT[k4 + 1][lr] = va.y;
                sAgT[k4 + 2][lr] = va.z;
                sAgT[k4 + 3][lr] = va.w;
                sAxT[k4 + 0][lr] = vx.x;
                sAxT[k4 + 1][lr] = vx.y;
                sAxT[k4 + 2][lr] = vx.z;
                sAxT[k4 + 3][lr] = vx.w;
            }
            // --- W tiles: duplicated float2 stores ---
            #pragma unroll
            for (int i = 0; i < 4; i++) {
                int kk = wk * 4 + i;
                int n = ncb + wn;
                float vl = 0.f, vr = 0.f;
                if (n < NTOT) {
                    vl = Wl[(size_t)(kb + kk) * NTOT + n];
                    vr = Wr[(size_t)(kb + kk) * NTOT + n];
                }
                *(float2*)&sWl2[kk][2 * wn] = make_float2(vl, vl);
                *(float2*)&sWr2[kk][2 * wn] = make_float2(vr, vr);
            }
            __syncthreads();

            #pragma unroll
            for (int k = 0; k < KB; k++) {
                ulonglong2 ag  = *(const ulonglong2*)&sAgT[k][r0];       // pairs (r0,r0+1),(r0+2,r0+3)
                ulonglong2 ax  = *(const ulonglong2*)&sAxT[k][r0];
                ulonglong2 wl0 = *(const ulonglong2*)&sWl2[k][2 * c0];       // (c0,c0) (c0+1,c0+1)
                ulonglong2 wl1 = *(const ulonglong2*)&sWl2[k][2 * c0 + 4];   // (c0+2..) (c0+3..)
                ulonglong2 wr0 = *(const ulonglong2*)&sWr2[k][2 * c0];
                ulonglong2 wr1 = *(const ulonglong2*)&sWr2[k][2 * c0 + 4];

                FMA_F32X2(acc[0][0], ag.x, wl0.x, acc[0][0]);
                FMA_F32X2(acc[0][1], ag.x, wl0.y, acc[0][1]);
                FMA_F32X2(acc[0][2], ag.x, wl1.x, acc[0][2]);
                FMA_F32X2(acc[0][3], ag.x, wl1.y, acc[0][3]);
                FMA_F32X2(acc[1][0], ag.y, wl0.x, acc[1][0]);
                FMA_F32X2(acc[1][1], ag.y, wl0.y, acc[1][1]);
                FMA_F32X2(acc[1][2], ag.y, wl1.x, acc[1][2]);
                FMA_F32X2(acc[1][3], ag.y, wl1.y, acc[1][3]);

                FMA_F32X2(acc[0][0], ax.x, wr0.x, acc[0][0]);
                FMA_F32X2(acc[0][1], ax.x, wr0.y, acc[0][1]);
                FMA_F32X2(acc[0][2], ax.x, wr1.x, acc[0][2]);
                FMA_F32X2(acc[0][3], ax.x, wr1.y, acc[0][3]);
                FMA_F32X2(acc[1][0], ax.y, wr0.x, acc[1][0]);
                FMA_F32X2(acc[1][1], ax.y, wr0.y, acc[1][1]);
                FMA_F32X2(acc[1][2], ax.y, wr1.x, acc[1][2]);
                FMA_F32X2(acc[1][3], ax.y, wr1.y, acc[1][3]);
            }
            __syncthreads();
        }

        // --- epilogue: unpack pairs, bias (+ReLU), float4 stores ---
        int n0 = ncb + c0;
        if (n0 < NTOT) {                         // NTOT % 4 == 0, so whole float4 valid
            float4 bv = *(const float4*)(bias + n0);
            #pragma unroll
            for (int p = 0; p < 2; p++) {
                float2 v0 = unpack_f32x2(acc[p][0]);
                float2 v1 = unpack_f32x2(acc[p][1]);
                float2 v2 = unpack_f32x2(acc[p][2]);
                float2 v3 = unpack_f32x2(acc[p][3]);
                #pragma unroll
                for (int s = 0; s < 2; s++) {
                    int m = mBase + r0 + 2 * p + s;
                    if (m >= N_NODES) continue;
                    float4 o;
                    o.x = (s ? v0.y : v0.x) + bv.x;
                    o.y = (s ? v1.y : v1.x) + bv.y;
                    o.z = (s ? v2.y : v2.x) + bv.z;
                    o.w = (s ? v3.y : v3.x) + bv.w;
                    if (RELU) {
                        o.x = fmaxf(o.x, 0.f); o.y = fmaxf(o.y, 0.f);
                        o.z = fmaxf(o.z, 0.f); o.w = fmaxf(o.w, 0.f);
                    }
                    *(float4*)(C + (size_t)m * NTOT + n0) = o;
                }
            }
        }
    }
}

// ---------------- launch ----------------
extern "C" void kernel_launch(void* const* d_in, const int* in_sizes, int n_in,
                              void* d_out, int out_size) {
    const float* x   = (const float*)d_in[0];
    const void*  ei  = d_in[1];                  // int32 or int64 — probed on device
    const float* W1l = (const float*)d_in[2];
    const float* b1  = (const float*)d_in[3];
    const float* W1r = (const float*)d_in[4];
    const float* W2l = (const float*)d_in[5];
    const float* b2  = (const float*)d_in[6];
    const float* W2r = (const float*)d_in[7];
    float* out = (float*)d_out;

    float* agg = nullptr; float* h = nullptr;
    cudaGetSymbolAddress((void**)&agg, g_agg);
    cudaGetSymbolAddress((void**)&h, g_h);

    const int TB = 256;

    // edge-index decode (dtype-agnostic)
    k_probe<<<1, 512>>>((const int*)ei);
    k_decode<<<(2 * N_EDGES + TB - 1) / TB, TB>>>(ei);

    // CSR build
    k_zero_cnt<<<(N_NODES + TB - 1) / TB, TB>>>();
    k_hist<<<(N_EDGES + TB - 1) / TB, TB>>>();
    k_scan<<<1, 1024>>>();
    k_scatter<<<(N_EDGES + TB - 1) / TB, TB>>>();

    // layer 1
    int aggBlocks = (N_NODES * 32 + TB - 1) / TB;
    k_agg<IN_DIM><<<aggBlocks, TB>>>(x, agg);
    int gemmBlocks = (N_NODES + 63) / 64;
    k_gemm<IN_DIM, HID_DIM, true><<<gemmBlocks, TB>>>(agg, x, W1l, W1r, b1, h);

    // layer 2
    k_agg<HID_DIM><<<aggBlocks, TB>>>(h, agg);
    k_gemm<HID_DIM, OUT_DIM, false><<<gemmBlocks, TB>>>(agg, h, W2l, W2r, b2, out);
}

// round 7
// speedup vs baseline: 1.9687x; 1.9687x over previous
#include <cuda_runtime.h>
#include <cstdint>

#define N_NODES 100000
#define N_EDGES 800000
#define IN_DIM 128
#define HID_DIM 256
#define OUT_DIM 40

// ---------------- scratch (device globals; no allocation allowed) ----------------
__device__ int   g_is64;
__device__ int   g_eidx[2 * N_EDGES];            // decoded edge index (src | dst)
__device__ int   g_cnt[N_NODES];
__device__ int   g_rowptr[N_NODES + 1];
__device__ int   g_cursor[N_NODES];
__device__ int   g_perm[N_EDGES];
__device__ float g_agg[(size_t)N_NODES * 128];   // layer-1 mean aggregate
__device__ float g_h[(size_t)N_NODES * 256];     // hidden layer
__device__ float g_P[(size_t)N_NODES * 40];      // h @ W2l   (pre-aggregation)
__device__ float g_Q[(size_t)N_NODES * 40];      // h @ W2r + b2

// ---------------- small helpers ----------------
__device__ __forceinline__ float4 f4add(float4 a, float4 b) {
    a.x += b.x; a.y += b.y; a.z += b.z; a.w += b.w; return a;
}
__device__ __forceinline__ float4 f4scale(float4 a, float s) {
    a.x *= s; a.y *= s; a.z *= s; a.w *= s; return a;
}

// ---------------- edge-index dtype probe + decode ----------------
__global__ void k_probe(const int* __restrict__ buf) {
    __shared__ int ok;
    if (threadIdx.x == 0) ok = 1;
    __syncthreads();
    int i = threadIdx.x;                 // 512 threads, pairs 0..511
    int lo = buf[2 * i];
    int hi = buf[2 * i + 1];
    if (!(hi == 0 && lo >= 0 && lo < N_NODES)) atomicAnd(&ok, 0);
    __syncthreads();
    if (threadIdx.x == 0) g_is64 = ok;
}

__global__ void k_decode(const void* __restrict__ buf) {
    int e = blockIdx.x * blockDim.x + threadIdx.x;
    if (e >= 2 * N_EDGES) return;
    int v;
    if (g_is64) v = (int)((const long long*)buf)[e];
    else        v = ((const int*)buf)[e];
    v = v < 0 ? 0 : (v >= N_NODES ? N_NODES - 1 : v);
    g_eidx[e] = v;
}

// ---------------- CSR construction ----------------
__global__ void k_zero_cnt() {
    int i = blockIdx.x * blockDim.x + threadIdx.x;
    if (i < N_NODES) g_cnt[i] = 0;
}

__global__ void k_hist() {
    int e = blockIdx.x * blockDim.x + threadIdx.x;
    if (e < N_EDGES) {
        int d = g_eidx[N_EDGES + e];
        atomicAdd(&g_cnt[d], 1);
    }
}

__global__ void k_scan() {
    const int T = 1024;
    const int CH = (N_NODES + T - 1) / T;
    int t = threadIdx.x;
    int beg = t * CH;
    int end = beg + CH; if (end > N_NODES) end = N_NODES;
    int s = 0;
    for (int i = beg; i < end; i++) s += g_cnt[i];

    __shared__ int ps[T];
    ps[t] = s;
    __syncthreads();
    for (int off = 1; off < T; off <<= 1) {
        int v = 0;
        if (t >= off) v = ps[t - off];
        __syncthreads();
        ps[t] += v;
        __syncthreads();
    }
    int run = ps[t] - s;
    for (int i = beg; i < end; i++) {
        g_rowptr[i] = run;
        g_cursor[i] = run;
        run += g_cnt[i];
    }
    if (t == 0) g_rowptr[N_NODES] = N_EDGES;
}

__global__ void k_scatter() {
    int e = blockIdx.x * blockDim.x + threadIdx.x;
    if (e < N_EDGES) {
        int s = g_eidx[e];
        int d = g_eidx[N_EDGES + e];
        int pos = atomicAdd(&g_cursor[d], 1);
        g_perm[pos] = s;
    }
}

// ---------------- mean aggregation (layer 1): one warp per node, no atomics ----------------
__global__ void __launch_bounds__(256) k_agg128(const float* __restrict__ feat,
                                                float* __restrict__ out) {
    int warp = (blockIdx.x * blockDim.x + threadIdx.x) >> 5;
    if (warp >= N_NODES) return;
    int lane = threadIdx.x & 31;

    int beg = g_rowptr[warp];
    int end = g_rowptr[warp + 1];

    float4 a0 = make_float4(0.f, 0.f, 0.f, 0.f);
    for (int e = beg; e < end; e++) {
        int s = g_perm[e];
        const float4* row = (const float4*)(feat + (size_t)s * 128);
        a0 = f4add(a0, row[lane]);
    }
    int deg = end - beg;
    float inv = 1.0f / (float)(deg > 0 ? deg : 1);
    ((float4*)(out + (size_t)warp * 128))[lane] = f4scale(a0, inv);
}

// ---------------- fused layer-2 aggregation + epilogue ----------------
// out[n] = mean_{src in N(n)} P[src]  +  Q[n]      (40 floats per node)
__global__ void __launch_bounds__(256) k_agg40_add(const float* __restrict__ P,
                                                   const float* __restrict__ Q,
                                                   float* __restrict__ out) {
    int warp = (blockIdx.x * blockDim.x + threadIdx.x) >> 5;
    if (warp >= N_NODES) return;
    int lane = threadIdx.x & 31;
    if (lane >= 10) return;              // 40 floats = 10 float4 slots

    int beg = g_rowptr[warp];
    int end = g_rowptr[warp + 1];

    float4 a = make_float4(0.f, 0.f, 0.f, 0.f);
    for (int e = beg; e < end; e++) {
        int s = g_perm[e];
        a = f4add(a, ((const float4*)(P + (size_t)s * 40))[lane]);
    }
    int deg = end - beg;
    float inv = 1.0f / (float)(deg > 0 ? deg : 1);
    float4 q = ((const float4*)(Q + (size_t)warp * 40))[lane];
    float4 o = f4add(f4scale(a, inv), q);
    ((float4*)(out + (size_t)warp * 40))[lane] = o;
}

// ---------------- fused SAGE GEMM (layer 1):  h = relu( Aagg@Wl + b + Ax@Wr ) ----------------
// Round-4 known-good structure. K=128, NTOT=256.
template <int K, int NTOT, bool RELU>
__global__ void __launch_bounds__(256) k_gemm(const float* __restrict__ Aagg,
                                              const float* __restrict__ Ax,
                                              const float* __restrict__ Wl,
                                              const float* __restrict__ Wr,
                                              const float* __restrict__ bias,
                                              float* __restrict__ C) {
    constexpr int BM = 64, NC = 64, KB = 32;
    __shared__ float sAg[BM][KB + 1];
    __shared__ float sAx[BM][KB + 1];
    __shared__ float sWl[KB][NC];
    __shared__ float sWr[KB][NC];

    int tid = threadIdx.x;
    int mBase = blockIdx.x * BM;
    int tx = tid & 15, ty = tid >> 4;
    int r0 = ty * 4, c0 = tx * 4;
    int lr = tid >> 3, lc = tid & 7;     // A tile loader: 32 rows x 8 float4-cols
    int wn = tid & 63, wk0 = tid >> 6;   // W tile loader: col wn, rows wk0 + 4*i

    for (int ncb = 0; ncb < NTOT; ncb += NC) {
        float acc[4][4];
        #pragma unroll
        for (int i = 0; i < 4; i++)
            #pragma unroll
            for (int j = 0; j < 4; j++) acc[i][j] = 0.f;

        for (int kb = 0; kb < K; kb += KB) {
            #pragma unroll
            for (int rr = 0; rr < BM; rr += 32) {
                int m = mBase + lr + rr;
                float4 va = make_float4(0.f, 0.f, 0.f, 0.f);
                float4 vx = va;
                if (m < N_NODES) {
                    va = *(const float4*)(Aagg + (size_t)m * K + kb + lc * 4);
                    vx = *(const float4*)(Ax   + (size_t)m * K + kb + lc * 4);
                }
                sAg[lr + rr][lc * 4 + 0] = va.x;
                sAg[lr + rr][lc * 4 + 1] = va.y;
                sAg[lr + rr][lc * 4 + 2] = va.z;
                sAg[lr + rr][lc * 4 + 3] = va.w;
                sAx[lr + rr][lc * 4 + 0] = vx.x;
                sAx[lr + rr][lc * 4 + 1] = vx.y;
                sAx[lr + rr][lc * 4 + 2] = vx.z;
                sAx[lr + rr][lc * 4 + 3] = vx.w;
            }
            #pragma unroll
            for (int kk = wk0; kk < KB; kk += 4) {
                int n = ncb + wn;
                float vl = 0.f, vr = 0.f;
                if (n < NTOT) {
                    vl = Wl[(size_t)(kb + kk) * NTOT + n];
                    vr = Wr[(size_t)(kb + kk) * NTOT + n];
                }
                sWl[kk][wn] = vl;
                sWr[kk][wn] = vr;
            }
            __syncthreads();

            #pragma unroll
            for (int k = 0; k < KB; k++) {
                float4 wl  = *(const float4*)&sWl[k][c0];
                float4 wr4 = *(const float4*)&sWr[k][c0];
                #pragma unroll
                for (int i = 0; i < 4; i++) {
                    float ag = sAg[r0 + i][k];
                    float ax = sAx[r0 + i][k];
                    acc[i][0] += ag * wl.x + ax * wr4.x;
                    acc[i][1] += ag * wl.y + ax * wr4.y;
                    acc[i][2] += ag * wl.z + ax * wr4.z;
                    acc[i][3] += ag * wl.w + ax * wr4.w;
                }
            }
            __syncthreads();
        }

        #pragma unroll
        for (int i = 0; i < 4; i++) {
            int m = mBase + r0 + i;
            if (m >= N_NODES) continue;
            #pragma unroll
            for (int j = 0; j < 4; j++) {
                int n = ncb + c0 + j;
                if (n >= NTOT) continue;
                float v = acc[i][j] + bias[n];
                if (RELU) v = fmaxf(v, 0.f);
                C[(size_t)m * NTOT + n] = v;
            }
        }
    }
}

// ---------------- layer-2 dual GEMM:  P = h@W2l,  Q = h@W2r + b2   (N=40, no padding) ----------------
// BM=64 rows x 40 cols, 160 threads, 4x4 per thread (tx 0..9, ty 0..15).
__global__ void __launch_bounds__(160) k_gemm2(const float* __restrict__ A,
                                               const float* __restrict__ Wl,
                                               const float* __restrict__ Wr,
                                               const float* __restrict__ bias,
                                               float* __restrict__ P,
                                               float* __restrict__ Q) {
    constexpr int K = HID_DIM, NTOT = OUT_DIM, BM = 64, KB = 32;
    __shared__ float sA[BM][KB + 1];
    __shared__ float sWl[KB][NTOT];
    __shared__ float sWr[KB][NTOT];

    int tid = threadIdx.x;
    int mBase = blockIdx.x * BM;
    int tx = tid % 10, ty = tid / 10;    // ty 0..15
    int r0 = ty * 4, c0 = tx * 4;

    float accP[4][4], accQ[4][4];
    #pragma unroll
    for (int i = 0; i < 4; i++)
        #pragma unroll
        for (int j = 0; j < 4; j++) { accP[i][j] = 0.f; accQ[i][j] = 0.f; }

    for (int kb = 0; kb < K; kb += KB) {
        // A tile: 64x32 floats = 512 float4, strided over 160 threads
        for (int idx = tid; idx < BM * (KB / 4); idx += 160) {
            int row = idx >> 3, c4 = idx & 7;
            int m = mBase + row;
            float4 v = make_float4(0.f, 0.f, 0.f, 0.f);
            if (m < N_NODES) v = *(const float4*)(A + (size_t)m * K + kb + c4 * 4);
            sA[row][c4 * 4 + 0] = v.x;
            sA[row][c4 * 4 + 1] = v.y;
            sA[row][c4 * 4 + 2] = v.z;
            sA[row][c4 * 4 + 3] = v.w;
        }
        // W tiles: 32x40 floats each, strided
        for (int idx = tid; idx < KB * NTOT; idx += 160) {
            int k = idx / NTOT, n = idx % NTOT;
            sWl[k][n] = Wl[(size_t)(kb + k) * NTOT + n];
            sWr[k][n] = Wr[(size_t)(kb + k) * NTOT + n];
        }
        __syncthreads();

        #pragma unroll
        for (int k = 0; k < KB; k++) {
            float4 wl = *(const float4*)&sWl[k][c0];
            float4 wr = *(const float4*)&sWr[k][c0];
            #pragma unroll
            for (int i = 0; i < 4; i++) {
                float a = sA[r0 + i][k];
                accP[i][0] += a * wl.x;
                accP[i][1] += a * wl.y;
                accP[i][2] += a * wl.z;
                accP[i][3] += a * wl.w;
                accQ[i][0] += a * wr.x;
                accQ[i][1] += a * wr.y;
                accQ[i][2] += a * wr.z;
                accQ[i][3] += a * wr.w;
            }
        }
        __syncthreads();
    }

    float4 bv = *(const float4*)(bias + c0);
    #pragma unroll
    for (int i = 0; i < 4; i++) {
        int m = mBase + r0 + i;
        if (m >= N_NODES) continue;
        float4 p = make_float4(accP[i][0], accP[i][1], accP[i][2], accP[i][3]);
        float4 q = make_float4(accQ[i][0] + bv.x, accQ[i][1] + bv.y,
                               accQ[i][2] + bv.z, accQ[i][3] + bv.w);
        *(float4*)(P + (size_t)m * NTOT + c0) = p;
        *(float4*)(Q + (size_t)m * NTOT + c0) = q;
    }
}

// ---------------- launch ----------------
extern "C" void kernel_launch(void* const* d_in, const int* in_sizes, int n_in,
                              void* d_out, int out_size) {
    const float* x   = (const float*)d_in[0];
    const void*  ei  = d_in[1];                  // int32 or int64 — probed on device
    const float* W1l = (const float*)d_in[2];
    const float* b1  = (const float*)d_in[3];
    const float* W1r = (const float*)d_in[4];
    const float* W2l = (const float*)d_in[5];
    const float* b2  = (const float*)d_in[6];
    const float* W2r = (const float*)d_in[7];
    float* out = (float*)d_out;

    float *agg = nullptr, *h = nullptr, *P = nullptr, *Q = nullptr;
    cudaGetSymbolAddress((void**)&agg, g_agg);
    cudaGetSymbolAddress((void**)&h, g_h);
    cudaGetSymbolAddress((void**)&P, g_P);
    cudaGetSymbolAddress((void**)&Q, g_Q);

    const int TB = 256;

    // edge-index decode (dtype-agnostic)
    k_probe<<<1, 512>>>((const int*)ei);
    k_decode<<<(2 * N_EDGES + TB - 1) / TB, TB>>>(ei);

    // CSR build
    k_zero_cnt<<<(N_NODES + TB - 1) / TB, TB>>>();
    k_hist<<<(N_EDGES + TB - 1) / TB, TB>>>();
    k_scan<<<1, 1024>>>();
    k_scatter<<<(N_EDGES + TB - 1) / TB, TB>>>();

    int aggBlocks = (N_NODES * 32 + TB - 1) / TB;
    int gemmBlocks = (N_NODES + 63) / 64;

    // layer 1: agg(x) -> fused GEMM -> h
    k_agg128<<<aggBlocks, TB>>>(x, agg);
    k_gemm<IN_DIM, HID_DIM, true><<<gemmBlocks, TB>>>(agg, x, W1l, W1r, b1, h);

    // layer 2 (aggregation commuted past the projection):
    //   P = h@W2l, Q = h@W2r + b2;  out = mean_agg(P) + Q
    k_gemm2<<<gemmBlocks, 160>>>(h, W2l, W2r, b2, P, Q);
    k_agg40_add<<<aggBlocks, TB>>>(P, Q, out);
}

// round 8
// speedup vs baseline: 2.8725x; 1.4591x over previous
#include <cuda_runtime.h>
#include <cstdint>

#define N_NODES 100000
#define N_EDGES 800000
#define IN_DIM 128
#define HID_DIM 256
#define OUT_DIM 40

// ---------------- scratch (device globals; no allocation allowed) ----------------
__device__ int   g_is64;
__device__ int   g_eidx[2 * N_EDGES];            // decoded edge index (src | dst)
__device__ int   g_cnt[N_NODES];
__device__ int   g_rowptr[N_NODES + 1];
__device__ int   g_cursor[N_NODES];
__device__ int   g_perm[N_EDGES];
__device__ float g_agg[(size_t)N_NODES * 128];   // layer-1 mean aggregate
__device__ float g_h[(size_t)N_NODES * 256];     // hidden layer
__device__ float g_P[(size_t)N_NODES * 40];      // h @ W2l   (pre-aggregation)
__device__ float g_Q[(size_t)N_NODES * 40];      // h @ W2r + b2

// ---------------- small helpers ----------------
__device__ __forceinline__ float4 f4add(float4 a, float4 b) {
    a.x += b.x; a.y += b.y; a.z += b.z; a.w += b.w; return a;
}
__device__ __forceinline__ float4 f4scale(float4 a, float s) {
    a.x *= s; a.y *= s; a.z *= s; a.w *= s; return a;
}
__device__ __forceinline__ float cvt_tf32(float x) {
    float y;
    asm("cvt.rna.tf32.f32 %0, %1;" : "=f"(y) : "f"(x));
    return y;
}
__device__ __forceinline__ float4 cvt4_tf32(float4 v) {
    v.x = cvt_tf32(v.x); v.y = cvt_tf32(v.y);
    v.z = cvt_tf32(v.z); v.w = cvt_tf32(v.w);
    return v;
}
__device__ __forceinline__ void mma_tf32(float& d0, float& d1, float& d2, float& d3,
                                         uint32_t a0, uint32_t a1, uint32_t a2, uint32_t a3,
                                         uint32_t b0, uint32_t b1) {
    asm volatile("mma.sync.aligned.m16n8k8.row.col.f32.tf32.tf32.f32 "
                 "{%0,%1,%2,%3}, {%4,%5,%6,%7}, {%8,%9}, {%0,%1,%2,%3};"
                 : "+f"(d0), "+f"(d1), "+f"(d2), "+f"(d3)
                 : "r"(a0), "r"(a1), "r"(a2), "r"(a3), "r"(b0), "r"(b1));
}

// ---------------- edge-index dtype probe + decode ----------------
__global__ void k_probe(const int* __restrict__ buf) {
    __shared__ int ok;
    if (threadIdx.x == 0) ok = 1;
    __syncthreads();
    int i = threadIdx.x;                 // 512 threads, pairs 0..511
    int lo = buf[2 * i];
    int hi = buf[2 * i + 1];
    if (!(hi == 0 && lo >= 0 && lo < N_NODES)) atomicAnd(&ok, 0);
    __syncthreads();
    if (threadIdx.x == 0) g_is64 = ok;
}

__global__ void k_decode(const void* __restrict__ buf) {
    int e = blockIdx.x * blockDim.x + threadIdx.x;
    if (e >= 2 * N_EDGES) return;
    int v;
    if (g_is64) v = (int)((const long long*)buf)[e];
    else        v = ((const int*)buf)[e];
    v = v < 0 ? 0 : (v >= N_NODES ? N_NODES - 1 : v);
    g_eidx[e] = v;
}

// ---------------- CSR construction ----------------
__global__ void k_zero_cnt() {
    int i = blockIdx.x * blockDim.x + threadIdx.x;
    if (i < N_NODES) g_cnt[i] = 0;
}

__global__ void k_hist() {
    int e = blockIdx.x * blockDim.x + threadIdx.x;
    if (e < N_EDGES) {
        int d = g_eidx[N_EDGES + e];
        atomicAdd(&g_cnt[d], 1);
    }
}

__global__ void k_scan() {
    const int T = 1024;
    const int CH = (N_NODES + T - 1) / T;
    int t = threadIdx.x;
    int beg = t * CH;
    int end = beg + CH; if (end > N_NODES) end = N_NODES;
    int s = 0;
    for (int i = beg; i < end; i++) s += g_cnt[i];

    __shared__ int ps[T];
    ps[t] = s;
    __syncthreads();
    for (int off = 1; off < T; off <<= 1) {
        int v = 0;
        if (t >= off) v = ps[t - off];
        __syncthreads();
        ps[t] += v;
        __syncthreads();
    }
    int run = ps[t] - s;
    for (int i = beg; i < end; i++) {
        g_rowptr[i] = run;
        g_cursor[i] = run;
        run += g_cnt[i];
    }
    if (t == 0) g_rowptr[N_NODES] = N_EDGES;
}

__global__ void k_scatter() {
    int e = blockIdx.x * blockDim.x + threadIdx.x;
    if (e < N_EDGES) {
        int s = g_eidx[e];
        int d = g_eidx[N_EDGES + e];
        int pos = atomicAdd(&g_cursor[d], 1);
        g_perm[pos] = s;
    }
}

// ---------------- mean aggregation (layer 1): one warp per node, no atomics ----------------
__global__ void __launch_bounds__(256) k_agg128(const float* __restrict__ feat,
                                                float* __restrict__ out) {
    int warp = (blockIdx.x * blockDim.x + threadIdx.x) >> 5;
    if (warp >= N_NODES) return;
    int lane = threadIdx.x & 31;

    int beg = g_rowptr[warp];
    int end = g_rowptr[warp + 1];

    float4 a0 = make_float4(0.f, 0.f, 0.f, 0.f);
    for (int e = beg; e < end; e++) {
        int s = g_perm[e];
        const float4* row = (const float4*)(feat + (size_t)s * 128);
        a0 = f4add(a0, row[lane]);
    }
    int deg = end - beg;
    float inv = 1.0f / (float)(deg > 0 ? deg : 1);
    ((float4*)(out + (size_t)warp * 128))[lane] = f4scale(a0, inv);
}

// ---------------- fused layer-2 aggregation + epilogue ----------------
// out[n] = mean_{src in N(n)} P[src]  +  Q[n]      (40 floats per node)
__global__ void __launch_bounds__(256) k_agg40_add(const float* __restrict__ P,
                                                   const float* __restrict__ Q,
                                                   float* __restrict__ out) {
    int warp = (blockIdx.x * blockDim.x + threadIdx.x) >> 5;
    if (warp >= N_NODES) return;
    int lane = threadIdx.x & 31;
    if (lane >= 10) return;              // 40 floats = 10 float4 slots

    int beg = g_rowptr[warp];
    int end = g_rowptr[warp + 1];

    float4 a = make_float4(0.f, 0.f, 0.f, 0.f);
    for (int e = beg; e < end; e++) {
        int s = g_perm[e];
        a = f4add(a, ((const float4*)(P + (size_t)s * 40))[lane]);
    }
    int deg = end - beg;
    float inv = 1.0f / (float)(deg > 0 ? deg : 1);
    float4 q = ((const float4*)(Q + (size_t)warp * 40))[lane];
    float4 o = f4add(f4scale(a, inv), q);
    ((float4*)(out + (size_t)warp * 40))[lane] = o;
}

// ---------------- layer-1 GEMM on tensor cores (TF32 mma.sync) ----------------
// h = relu( [Aagg | Ax] @ [W1l ; W1r] + b1 )   as one K=256 GEMM.
// BM=128, BN=64, BK=32; 8 warps in a 4x2 grid, warp tile 32x32 (2x4 m16n8k8).
__global__ void __launch_bounds__(256) k_gemm1_tc(const float* __restrict__ Aagg,
                                                  const float* __restrict__ Ax,
                                                  const float* __restrict__ Wl,
                                                  const float* __restrict__ Wr,
                                                  const float* __restrict__ bias,
                                                  float* __restrict__ C) {
    constexpr int BM = 128, BN = 64, BK = 32;
    __shared__ float sA[BM][36];   // pitch 36: conflict-free frag reads, 16B-aligned rows
    __shared__ float sW[BK][72];   // pitch 72: conflict-free frag reads, 16B-aligned rows

    int tid = threadIdx.x;
    int lane = tid & 31, wid = tid >> 5;
    int wm = wid >> 1, wn = wid & 1;         // warp grid 4(M) x 2(N)
    int mBase = blockIdx.x * BM;
    int nBase = blockIdx.y * BN;
    int lr = lane >> 2, lq = lane & 3;

    float d[2][4][4];
    #pragma unroll
    for (int mt = 0; mt < 2; mt++)
        #pragma unroll
        for (int nt = 0; nt < 4; nt++)
            #pragma unroll
            for (int j = 0; j < 4; j++) d[mt][nt][j] = 0.f;

    for (int kb = 0; kb < 256; kb += BK) {
        const float* Asrc = (kb < 128) ? Aagg : Ax;
        const float* Wsrc = (kb < 128) ? Wl : Wr;
        int kc = kb & 127;

        // A tile: 128 x 32, float4 loads, tf32-convert at store
        #pragma unroll
        for (int rr = 0; rr < 4; rr++) {
            int row = rr * 32 + (tid >> 3);
            int c4  = tid & 7;
            int m   = mBase + row;
            float4 v = make_float4(0.f, 0.f, 0.f, 0.f);
            if (m < N_NODES) v = *(const float4*)(Asrc + (size_t)m * 128 + kc + c4 * 4);
            *(float4*)&sA[row][c4 * 4] = cvt4_tf32(v);
        }
        // W tile: 32 x 64
        #pragma unroll
        for (int i = 0; i < 2; i++) {
            int kk = (tid >> 4) + i * 16;
            int c4 = tid & 15;
            float4 v = *(const float4*)(Wsrc + (size_t)(kc + kk) * 256 + nBase + c4 * 4);
            *(float4*)&sW[kk][c4 * 4] = cvt4_tf32(v);
        }
        __syncthreads();

        #pragma unroll
        for (int k8 = 0; k8 < 4; k8++) {
            int k0 = k8 * 8;
            uint32_t af[2][4], bf[4][2];
            #pragma unroll
            for (int mt = 0; mt < 2; mt++) {
                int rb = wm * 32 + mt * 16;
                af[mt][0] = __float_as_uint(sA[rb + lr][k0 + lq]);
                af[mt][1] = __float_as_uint(sA[rb + 8 + lr][k0 + lq]);
                af[mt][2] = __float_as_uint(sA[rb + lr][k0 + 4 + lq]);
                af[mt][3] = __float_as_uint(sA[rb + 8 + lr][k0 + 4 + lq]);
            }
            #pragma unroll
            for (int nt = 0; nt < 4; nt++) {
                int cb = wn * 32 + nt * 8;
                bf[nt][0] = __float_as_uint(sW[k0 + lq][cb + lr]);
                bf[nt][1] = __float_as_uint(sW[k0 + 4 + lq][cb + lr]);
            }
            #pragma unroll
            for (int mt = 0; mt < 2; mt++)
                #pragma unroll
                for (int nt = 0; nt < 4; nt++)
                    mma_tf32(d[mt][nt][0], d[mt][nt][1], d[mt][nt][2], d[mt][nt][3],
                             af[mt][0], af[mt][1], af[mt][2], af[mt][3],
                             bf[nt][0], bf[nt][1]);
        }
        __syncthreads();
    }

    // epilogue: bias + relu, float2 stores (c0,c1 are adjacent columns)
    #pragma unroll
    for (int mt = 0; mt < 2; mt++) {
        int rb = mBase + wm * 32 + mt * 16 + lr;
        #pragma unroll
        for (int nt = 0; nt < 4; nt++) {
            int c = nBase + wn * 32 + nt * 8 + lq * 2;
            float b0 = bias[c], b1 = bias[c + 1];
            if (rb < N_NODES) {
                float2 o;
                o.x = fmaxf(d[mt][nt][0] + b0, 0.f);
                o.y = fmaxf(d[mt][nt][1] + b1, 0.f);
                *(float2*)(C + (size_t)rb * 256 + c) = o;
            }
            if (rb + 8 < N_NODES) {
                float2 o;
                o.x = fmaxf(d[mt][nt][2] + b0, 0.f);
                o.y = fmaxf(d[mt][nt][3] + b1, 0.f);
                *(float2*)(C + (size_t)(rb + 8) * 256 + c) = o;
            }
        }
    }
}

// ---------------- layer-2 dual GEMM (exact fp32):  P = h@W2l,  Q = h@W2r + b2 ----------------
__global__ void __launch_bounds__(160) k_gemm2(const float* __restrict__ A,
                                               const float* __restrict__ Wl,
                                               const float* __restrict__ Wr,
                                               const float* __restrict__ bias,
                                               float* __restrict__ P,
                                               float* __restrict__ Q) {
    constexpr int K = HID_DIM, NTOT = OUT_DIM, BM = 64, KB = 32;
    __shared__ float sA[BM][KB + 1];
    __shared__ float sWl[KB][NTOT];
    __shared__ float sWr[KB][NTOT];

    int tid = threadIdx.x;
    int mBase = blockIdx.x * BM;
    int tx = tid % 10, ty = tid / 10;    // ty 0..15
    int r0 = ty * 4, c0 = tx * 4;

    float accP[4][4], accQ[4][4];
    #pragma unroll
    for (int i = 0; i < 4; i++)
        #pragma unroll
        for (int j = 0; j < 4; j++) { accP[i][j] = 0.f; accQ[i][j] = 0.f; }

    for (int kb = 0; kb < K; kb += KB) {
        for (int idx = tid; idx < BM * (KB / 4); idx += 160) {
            int row = idx >> 3, c4 = idx & 7;
            int m = mBase + row;
            float4 v = make_float4(0.f, 0.f, 0.f, 0.f);
            if (m < N_NODES) v = *(const float4*)(A + (size_t)m * K + kb + c4 * 4);
            sA[row][c4 * 4 + 0] = v.x;
            sA[row][c4 * 4 + 1] = v.y;
            sA[row][c4 * 4 + 2] = v.z;
            sA[row][c4 * 4 + 3] = v.w;
        }
        for (int idx = tid; idx < KB * NTOT; idx += 160) {
            int k = idx / NTOT, n = idx % NTOT;
            sWl[k][n] = Wl[(size_t)(kb + k) * NTOT + n];
            sWr[k][n] = Wr[(size_t)(kb + k) * NTOT + n];
        }
        __syncthreads();

        #pragma unroll
        for (int k = 0; k < KB; k++) {
            float4 wl = *(const float4*)&sWl[k][c0];
            float4 wr = *(const float4*)&sWr[k][c0];
            #pragma unroll
            for (int i = 0; i < 4; i++) {
                float a = sA[r0 + i][k];
                accP[i][0] += a * wl.x;
                accP[i][1] += a * wl.y;
                accP[i][2] += a * wl.z;
                accP[i][3] += a * wl.w;
                accQ[i][0] += a * wr.x;
                accQ[i][1] += a * wr.y;
                accQ[i][2] += a * wr.z;
                accQ[i][3] += a * wr.w;
            }
        }
        __syncthreads();
    }

    float4 bv = *(const float4*)(bias + c0);
    #pragma unroll
    for (int i = 0; i < 4; i++) {
        int m = mBase + r0 + i;
        if (m >= N_NODES) continue;
        float4 p = make_float4(accP[i][0], accP[i][1], accP[i][2], accP[i][3]);
        float4 q = make_float4(accQ[i][0] + bv.x, accQ[i][1] + bv.y,
                               accQ[i][2] + bv.z, accQ[i][3] + bv.w);
        *(float4*)(P + (size_t)m * NTOT + c0) = p;
        *(float4*)(Q + (size_t)m * NTOT + c0) = q;
    }
}

// ---------------- launch ----------------
extern "C" void kernel_launch(void* const* d_in, const int* in_sizes, int n_in,
                              void* d_out, int out_size) {
    const float* x   = (const float*)d_in[0];
    const void*  ei  = d_in[1];                  // int32 or int64 — probed on device
    const float* W1l = (const float*)d_in[2];
    const float* b1  = (const float*)d_in[3];
    const float* W1r = (const float*)d_in[4];
    const float* W2l = (const float*)d_in[5];
    const float* b2  = (const float*)d_in[6];
    const float* W2r = (const float*)d_in[7];
    float* out = (float*)d_out;

    float *agg = nullptr, *h = nullptr, *P = nullptr, *Q = nullptr;
    cudaGetSymbolAddress((void**)&agg, g_agg);
    cudaGetSymbolAddress((void**)&h, g_h);
    cudaGetSymbolAddress((void**)&P, g_P);
    cudaGetSymbolAddress((void**)&Q, g_Q);

    const int TB = 256;

    // edge-index decode (dtype-agnostic)
    k_probe<<<1, 512>>>((const int*)ei);
    k_decode<<<(2 * N_EDGES + TB - 1) / TB, TB>>>(ei);

    // CSR build
    k_zero_cnt<<<(N_NODES + TB - 1) / TB, TB>>>();
    k_hist<<<(N_EDGES + TB - 1) / TB, TB>>>();
    k_scan<<<1, 1024>>>();
    k_scatter<<<(N_EDGES + TB - 1) / TB, TB>>>();

    int aggBlocks = (N_NODES * 32 + TB - 1) / TB;

    // layer 1: agg(x) -> TF32 tensor-core GEMM -> h
    k_agg128<<<aggBlocks, TB>>>(x, agg);
    dim3 g1((N_NODES + 127) / 128, HID_DIM / 64);
    k_gemm1_tc<<<g1, 256>>>(agg, x, W1l, W1r, b1, h);

    // layer 2 (aggregation commuted past the projection):
    //   P = h@W2l, Q = h@W2r + b2;  out = mean_agg(P) + Q
    int gemmBlocks = (N_NODES + 63) / 64;
    k_gemm2<<<gemmBlocks, 160>>>(h, W2l, W2r, b2, P, Q);
    k_agg40_add<<<aggBlocks, TB>>>(P, Q, out);
}

// round 9
// speedup vs baseline: 3.4845x; 1.2131x over previous
#include <cuda_runtime.h>
#include <cstdint>

#define N_NODES 100000
#define N_EDGES 800000
#define IN_DIM 128
#define HID_DIM 256
#define OUT_DIM 40

// ---------------- scratch (device globals; no allocation allowed) ----------------
__device__ int   g_is64;
__device__ int   g_eidx[2 * N_EDGES];            // decoded edge index (src | dst)
__device__ int   g_cnt[N_NODES];
__device__ int   g_rowptr[N_NODES + 1];
__device__ int   g_cursor[N_NODES];
__device__ int   g_perm[N_EDGES];
__device__ float g_agg[(size_t)N_NODES * 128];   // layer-1 mean aggregate
__device__ float g_h[(size_t)N_NODES * 256];     // hidden layer
__device__ float g_P[(size_t)N_NODES * 40];      // h @ W2l   (pre-aggregation)
__device__ float g_Q[(size_t)N_NODES * 40];      // h @ W2r + b2

// ---------------- small helpers ----------------
__device__ __forceinline__ float4 f4add(float4 a, float4 b) {
    a.x += b.x; a.y += b.y; a.z += b.z; a.w += b.w; return a;
}
__device__ __forceinline__ float4 f4scale(float4 a, float s) {
    a.x *= s; a.y *= s; a.z *= s; a.w *= s; return a;
}
__device__ __forceinline__ float cvt_tf32(float x) {
    float y;
    asm("cvt.rna.tf32.f32 %0, %1;" : "=f"(y) : "f"(x));
    return y;
}
__device__ __forceinline__ float4 cvt4_tf32(float4 v) {
    v.x = cvt_tf32(v.x); v.y = cvt_tf32(v.y);
    v.z = cvt_tf32(v.z); v.w = cvt_tf32(v.w);
    return v;
}
__device__ __forceinline__ void mma_tf32(float& d0, float& d1, float& d2, float& d3,
                                         uint32_t a0, uint32_t a1, uint32_t a2, uint32_t a3,
                                         uint32_t b0, uint32_t b1) {
    asm volatile("mma.sync.aligned.m16n8k8.row.col.f32.tf32.tf32.f32 "
                 "{%0,%1,%2,%3}, {%4,%5,%6,%7}, {%8,%9}, {%0,%1,%2,%3};"
                 : "+f"(d0), "+f"(d1), "+f"(d2), "+f"(d3)
                 : "r"(a0), "r"(a1), "r"(a2), "r"(a3), "r"(b0), "r"(b1));
}

// ---------------- edge-index dtype probe + decode ----------------
__global__ void k_probe(const int* __restrict__ buf) {
    __shared__ int ok;
    if (threadIdx.x == 0) ok = 1;
    __syncthreads();
    int i = threadIdx.x;                 // 512 threads, pairs 0..511
    int lo = buf[2 * i];
    int hi = buf[2 * i + 1];
    if (!(hi == 0 && lo >= 0 && lo < N_NODES)) atomicAnd(&ok, 0);
    __syncthreads();
    if (threadIdx.x == 0) g_is64 = ok;
}

__global__ void k_decode(const void* __restrict__ buf) {
    int e = blockIdx.x * blockDim.x + threadIdx.x;
    if (e >= 2 * N_EDGES) return;
    int v;
    if (g_is64) v = (int)((const long long*)buf)[e];
    else        v = ((const int*)buf)[e];
    v = v < 0 ? 0 : (v >= N_NODES ? N_NODES - 1 : v);
    g_eidx[e] = v;
}

// ---------------- CSR construction ----------------
__global__ void k_zero_cnt() {
    int i = blockIdx.x * blockDim.x + threadIdx.x;
    if (i < N_NODES) g_cnt[i] = 0;
}

__global__ void k_hist() {
    int e = blockIdx.x * blockDim.x + threadIdx.x;
    if (e < N_EDGES) {
        int d = g_eidx[N_EDGES + e];
        atomicAdd(&g_cnt[d], 1);
    }
}

__global__ void k_scan() {
    const int T = 1024;
    const int CH = (N_NODES + T - 1) / T;
    int t = threadIdx.x;
    int beg = t * CH;
    int end = beg + CH; if (end > N_NODES) end = N_NODES;
    int s = 0;
    for (int i = beg; i < end; i++) s += g_cnt[i];

    __shared__ int ps[T];
    ps[t] = s;
    __syncthreads();
    for (int off = 1; off < T; off <<= 1) {
        int v = 0;
        if (t >= off) v = ps[t - off];
        __syncthreads();
        ps[t] += v;
        __syncthreads();
    }
    int run = ps[t] - s;
    for (int i = beg; i < end; i++) {
        g_rowptr[i] = run;
        g_cursor[i] = run;
        run += g_cnt[i];
    }
    if (t == 0) g_rowptr[N_NODES] = N_EDGES;
}

__global__ void k_scatter() {
    int e = blockIdx.x * blockDim.x + threadIdx.x;
    if (e < N_EDGES) {
        int s = g_eidx[e];
        int d = g_eidx[N_EDGES + e];
        int pos = atomicAdd(&g_cursor[d], 1);
        g_perm[pos] = s;
    }
}

// ---------------- mean aggregation (layer 1): one warp per node, no atomics ----------------
__global__ void __launch_bounds__(256) k_agg128(const float* __restrict__ feat,
                                                float* __restrict__ out) {
    int warp = (blockIdx.x * blockDim.x + threadIdx.x) >> 5;
    if (warp >= N_NODES) return;
    int lane = threadIdx.x & 31;

    int beg = g_rowptr[warp];
    int end = g_rowptr[warp + 1];

    float4 a0 = make_float4(0.f, 0.f, 0.f, 0.f);
    for (int e = beg; e < end; e++) {
        int s = g_perm[e];
        const float4* row = (const float4*)(feat + (size_t)s * 128);
        a0 = f4add(a0, row[lane]);
    }
    int deg = end - beg;
    float inv = 1.0f / (float)(deg > 0 ? deg : 1);
    ((float4*)(out + (size_t)warp * 128))[lane] = f4scale(a0, inv);
}

// ---------------- fused layer-2 aggregation + epilogue ----------------
// out[n] = mean_{src in N(n)} P[src]  +  Q[n]      (40 floats per node)
__global__ void __launch_bounds__(256) k_agg40_add(const float* __restrict__ P,
                                                   const float* __restrict__ Q,
                                                   float* __restrict__ out) {
    int warp = (blockIdx.x * blockDim.x + threadIdx.x) >> 5;
    if (warp >= N_NODES) return;
    int lane = threadIdx.x & 31;
    if (lane >= 10) return;              // 40 floats = 10 float4 slots

    int beg = g_rowptr[warp];
    int end = g_rowptr[warp + 1];

    float4 a = make_float4(0.f, 0.f, 0.f, 0.f);
    for (int e = beg; e < end; e++) {
        int s = g_perm[e];
        a = f4add(a, ((const float4*)(P + (size_t)s * 40))[lane]);
    }
    int deg = end - beg;
    float inv = 1.0f / (float)(deg > 0 ? deg : 1);
    float4 q = ((const float4*)(Q + (size_t)warp * 40))[lane];
    float4 o = f4add(f4scale(a, inv), q);
    ((float4*)(out + (size_t)warp * 40))[lane] = o;
}

// ---------------- layer-1 GEMM on tensor cores (TF32 mma.sync) ----------------
// h = relu( [Aagg | Ax] @ [W1l ; W1r] + b1 )   as one K=256 GEMM.
// BM=128, BN=64, BK=32; 8 warps in a 4x2 grid, warp tile 32x32 (2x4 m16n8k8).
__global__ void __launch_bounds__(256) k_gemm1_tc(const float* __restrict__ Aagg,
                                                  const float* __restrict__ Ax,
                                                  const float* __restrict__ Wl,
                                                  const float* __restrict__ Wr,
                                                  const float* __restrict__ bias,
                                                  float* __restrict__ C) {
    constexpr int BM = 128, BN = 64, BK = 32;
    __shared__ float sA[BM][36];   // pitch 36: conflict-free frag reads, 16B-aligned rows
    __shared__ float sW[BK][72];   // pitch 72: conflict-free frag reads, 16B-aligned rows

    int tid = threadIdx.x;
    int lane = tid & 31, wid = tid >> 5;
    int wm = wid >> 1, wn = wid & 1;         // warp grid 4(M) x 2(N)
    int mBase = blockIdx.x * BM;
    int nBase = blockIdx.y * BN;
    int lr = lane >> 2, lq = lane & 3;

    float d[2][4][4];
    #pragma unroll
    for (int mt = 0; mt < 2; mt++)
        #pragma unroll
        for (int nt = 0; nt < 4; nt++)
            #pragma unroll
            for (int j = 0; j < 4; j++) d[mt][nt][j] = 0.f;

    for (int kb = 0; kb < 256; kb += BK) {
        const float* Asrc = (kb < 128) ? Aagg : Ax;
        const float* Wsrc = (kb < 128) ? Wl : Wr;
        int kc = kb & 127;

        // A tile: 128 x 32, float4 loads, tf32-convert at store
        #pragma unroll
        for (int rr = 0; rr < 4; rr++) {
            int row = rr * 32 + (tid >> 3);
            int c4  = tid & 7;
            int m   = mBase + row;
            float4 v = make_float4(0.f, 0.f, 0.f, 0.f);
            if (m < N_NODES) v = *(const float4*)(Asrc + (size_t)m * 128 + kc + c4 * 4);
            *(float4*)&sA[row][c4 * 4] = cvt4_tf32(v);
        }
        // W tile: 32 x 64
        #pragma unroll
        for (int i = 0; i < 2; i++) {
            int kk = (tid >> 4) + i * 16;
            int c4 = tid & 15;
            float4 v = *(const float4*)(Wsrc + (size_t)(kc + kk) * 256 + nBase + c4 * 4);
            *(float4*)&sW[kk][c4 * 4] = cvt4_tf32(v);
        }
        __syncthreads();

        #pragma unroll
        for (int k8 = 0; k8 < 4; k8++) {
            int k0 = k8 * 8;
            uint32_t af[2][4], bf[4][2];
            #pragma unroll
            for (int mt = 0; mt < 2; mt++) {
                int rb = wm * 32 + mt * 16;
                af[mt][0] = __float_as_uint(sA[rb + lr][k0 + lq]);
                af[mt][1] = __float_as_uint(sA[rb + 8 + lr][k0 + lq]);
                af[mt][2] = __float_as_uint(sA[rb + lr][k0 + 4 + lq]);
                af[mt][3] = __float_as_uint(sA[rb + 8 + lr][k0 + 4 + lq]);
            }
            #pragma unroll
            for (int nt = 0; nt < 4; nt++) {
                int cb = wn * 32 + nt * 8;
                bf[nt][0] = __float_as_uint(sW[k0 + lq][cb + lr]);
                bf[nt][1] = __float_as_uint(sW[k0 + 4 + lq][cb + lr]);
            }
            #pragma unroll
            for (int mt = 0; mt < 2; mt++)
                #pragma unroll
                for (int nt = 0; nt < 4; nt++)
                    mma_tf32(d[mt][nt][0], d[mt][nt][1], d[mt][nt][2], d[mt][nt][3],
                             af[mt][0], af[mt][1], af[mt][2], af[mt][3],
                             bf[nt][0], bf[nt][1]);
        }
        __syncthreads();
    }

    // epilogue: bias + relu, float2 stores (c0,c1 are adjacent columns)
    #pragma unroll
    for (int mt = 0; mt < 2; mt++) {
        int rb = mBase + wm * 32 + mt * 16 + lr;
        #pragma unroll
        for (int nt = 0; nt < 4; nt++) {
            int c = nBase + wn * 32 + nt * 8 + lq * 2;
            float b0 = bias[c], b1 = bias[c + 1];
            if (rb < N_NODES) {
                float2 o;
                o.x = fmaxf(d[mt][nt][0] + b0, 0.f);
                o.y = fmaxf(d[mt][nt][1] + b1, 0.f);
                *(float2*)(C + (size_t)rb * 256 + c) = o;
            }
            if (rb + 8 < N_NODES) {
                float2 o;
                o.x = fmaxf(d[mt][nt][2] + b0, 0.f);
                o.y = fmaxf(d[mt][nt][3] + b1, 0.f);
                *(float2*)(C + (size_t)(rb + 8) * 256 + c) = o;
            }
        }
    }
}

// ---------------- layer-2 dual GEMM on tensor cores (TF32 mma.sync) ----------------
// P = h @ W2l,  Q = h @ W2r + b2   as one K=256, N=80 GEMM (W2l || W2r).
// BM=128, BN=80, BK=32; 8 warps 4(M)x2(N); warp tile 32x40 = 2x5 m16n8k8 tiles.
// warp-n 0 -> P columns 0..39, warp-n 1 -> Q columns 0..39.
__global__ void __launch_bounds__(256) k_gemm2_tc(const float* __restrict__ A,
                                                  const float* __restrict__ Wl,
                                                  const float* __restrict__ Wr,
                                                  const float* __restrict__ bias,
                                                  float* __restrict__ P,
                                                  float* __restrict__ Q) {
    constexpr int BM = 128, BK = 32;
    __shared__ float sA[BM][36];   // pitch 36: conflict-free (proven in gemm1)
    __shared__ float sW[BK][88];   // 80 cols + pad; bank = (24*lq + c) mod 32 -> conflict-free

    int tid = threadIdx.x;
    int lane = tid & 31, wid = tid >> 5;
    int wm = wid >> 1, wn = wid & 1;
    int mBase = blockIdx.x * BM;
    int lr = lane >> 2, lq = lane & 3;

    float d[2][5][4];
    #pragma unroll
    for (int mt = 0; mt < 2; mt++)
        #pragma unroll
        for (int nt = 0; nt < 5; nt++)
            #pragma unroll
            for (int j = 0; j < 4; j++) d[mt][nt][j] = 0.f;

    for (int kb = 0; kb < 256; kb += BK) {
        // A tile: 128 x 32 from h (row stride 256)
        #pragma unroll
        for (int rr = 0; rr < 4; rr++) {
            int row = rr * 32 + (tid >> 3);
            int c4  = tid & 7;
            int m   = mBase + row;
            float4 v = make_float4(0.f, 0.f, 0.f, 0.f);
            if (m < N_NODES) v = *(const float4*)(A + (size_t)m * 256 + kb + c4 * 4);
            *(float4*)&sA[row][c4 * 4] = cvt4_tf32(v);
        }
        // W tiles: Wl -> cols [0,40), Wr -> cols [40,80). 32 rows x 10 float4 each.
        for (int idx = tid; idx < 320; idx += 256) {
            int kk = idx / 10, c4 = idx % 10;
            float4 v = *(const float4*)(Wl + (size_t)(kb + kk) * 40 + c4 * 4);
            *(float4*)&sW[kk][c4 * 4] = cvt4_tf32(v);
        }
        for (int idx = tid; idx < 320; idx += 256) {
            int kk = idx / 10, c4 = idx % 10;
            float4 v = *(const float4*)(Wr + (size_t)(kb + kk) * 40 + c4 * 4);
            *(float4*)&sW[kk][40 + c4 * 4] = cvt4_tf32(v);
        }
        __syncthreads();

        #pragma unroll
        for (int k8 = 0; k8 < 4; k8++) {
            int k0 = k8 * 8;
            uint32_t af[2][4], bf[5][2];
            #pragma unroll
            for (int mt = 0; mt < 2; mt++) {
                int rb = wm * 32 + mt * 16;
                af[mt][0] = __float_as_uint(sA[rb + lr][k0 + lq]);
                af[mt][1] = __float_as_uint(sA[rb + 8 + lr][k0 + lq]);
                af[mt][2] = __float_as_uint(sA[rb + lr][k0 + 4 + lq]);
                af[mt][3] = __float_as_uint(sA[rb + 8 + lr][k0 + 4 + lq]);
            }
            #pragma unroll
            for (int nt = 0; nt < 5; nt++) {
                int cb = wn * 40 + nt * 8;
                bf[nt][0] = __float_as_uint(sW[k0 + lq][cb + lr]);
                bf[nt][1] = __float_as_uint(sW[k0 + 4 + lq][cb + lr]);
            }
            #pragma unroll
            for (int mt = 0; mt < 2; mt++)
                #pragma unroll
                for (int nt = 0; nt < 5; nt++)
                    mma_tf32(d[mt][nt][0], d[mt][nt][1], d[mt][nt][2], d[mt][nt][3],
                             af[mt][0], af[mt][1], af[mt][2], af[mt][3],
                             bf[nt][0], bf[nt][1]);
        }
        __syncthreads();
    }

    // epilogue: wn=0 -> P (no bias), wn=1 -> Q (+bias)
    float* dst = wn ? Q : P;
    #pragma unroll
    for (int mt = 0; mt < 2; mt++) {
        int rb = mBase + wm * 32 + mt * 16 + lr;
        #pragma unroll
        for (int nt = 0; nt < 5; nt++) {
            int cc = nt * 8 + lq * 2;        // output column 0..38 (even)
            float b0 = wn ? bias[cc] : 0.f;
            float b1 = wn ? bias[cc + 1] : 0.f;
            if (rb < N_NODES) {
                float2 o = make_float2(d[mt][nt][0] + b0, d[mt][nt][1] + b1);
                *(float2*)(dst + (size_t)rb * 40 + cc) = o;
            }
            if (rb + 8 < N_NODES) {
                float2 o = make_float2(d[mt][nt][2] + b0, d[mt][nt][3] + b1);
                *(float2*)(dst + (size_t)(rb + 8) * 40 + cc) = o;
            }
        }
    }
}

// ---------------- launch ----------------
extern "C" void kernel_launch(void* const* d_in, const int* in_sizes, int n_in,
                              void* d_out, int out_size) {
    const float* x   = (const float*)d_in[0];
    const void*  ei  = d_in[1];                  // int32 or int64 — probed on device
    const float* W1l = (const float*)d_in[2];
    const float* b1  = (const float*)d_in[3];
    const float* W1r = (const float*)d_in[4];
    const float* W2l = (const float*)d_in[5];
    const float* b2  = (const float*)d_in[6];
    const float* W2r = (const float*)d_in[7];
    float* out = (float*)d_out;

    float *agg = nullptr, *h = nullptr, *P = nullptr, *Q = nullptr;
    cudaGetSymbolAddress((void**)&agg, g_agg);
    cudaGetSymbolAddress((void**)&h, g_h);
    cudaGetSymbolAddress((void**)&P, g_P);
    cudaGetSymbolAddress((void**)&Q, g_Q);

    const int TB = 256;

    // edge-index decode (dtype-agnostic)
    k_probe<<<1, 512>>>((const int*)ei);
    k_decode<<<(2 * N_EDGES + TB - 1) / TB, TB>>>(ei);

    // CSR build
    k_zero_cnt<<<(N_NODES + TB - 1) / TB, TB>>>();
    k_hist<<<(N_EDGES + TB - 1) / TB, TB>>>();
    k_scan<<<1, 1024>>>();
    k_scatter<<<(N_EDGES + TB - 1) / TB, TB>>>();

    int aggBlocks = (N_NODES * 32 + TB - 1) / TB;

    // layer 1: agg(x) -> TF32 tensor-core GEMM -> h
    k_agg128<<<aggBlocks, TB>>>(x, agg);
    dim3 g1((N_NODES + 127) / 128, HID_DIM / 64);
    k_gemm1_tc<<<g1, 256>>>(agg, x, W1l, W1r, b1, h);

    // layer 2 (aggregation commuted past the projection):
    //   P = h@W2l, Q = h@W2r + b2;  out = mean_agg(P) + Q
    k_gemm2_tc<<<(N_NODES + 127) / 128, 256>>>(h, W2l, W2r, b2, P, Q);
    k_agg40_add<<<aggBlocks, TB>>>(P, Q, out);
}

// round 14
// speedup vs baseline: 3.9888x; 1.1447x over previous
#include <cuda_runtime.h>
#include <cstdint>

#define N_NODES 100000
#define N_EDGES 800000
#define IN_DIM 128
#define HID_DIM 256
#define OUT_DIM 40

// ---------------- scratch (device globals; no allocation allowed) ----------------
__device__ int   g_is64;
__device__ int   g_eidx[2 * N_EDGES];            // decoded edge index (src | dst)
__device__ int   g_cnt[N_NODES];
__device__ int   g_rowptr[N_NODES + 1];
__device__ int   g_cursor[N_NODES];
__device__ int   g_perm[N_EDGES];
__device__ float g_agg[(size_t)N_NODES * 128];   // layer-1 mean aggregate
__device__ float g_h[(size_t)N_NODES * 256];     // hidden layer
__device__ float g_P[(size_t)N_NODES * 40];      // h @ W2l   (pre-aggregation)
__device__ float g_Q[(size_t)N_NODES * 40];      // h @ W2r + b2

// ---------------- small helpers ----------------
__device__ __forceinline__ float4 f4add(float4 a, float4 b) {
    a.x += b.x; a.y += b.y; a.z += b.z; a.w += b.w; return a;
}
__device__ __forceinline__ float4 f4scale(float4 a, float s) {
    a.x *= s; a.y *= s; a.z *= s; a.w *= s; return a;
}
__device__ __forceinline__ float cvt_tf32(float x) {
    float y;
    asm("cvt.rna.tf32.f32 %0, %1;" : "=f"(y) : "f"(x));
    return y;
}
__device__ __forceinline__ float4 cvt4_tf32(float4 v) {
    v.x = cvt_tf32(v.x); v.y = cvt_tf32(v.y);
    v.z = cvt_tf32(v.z); v.w = cvt_tf32(v.w);
    return v;
}
__device__ __forceinline__ void mma_tf32(float& d0, float& d1, float& d2, float& d3,
                                         uint32_t a0, uint32_t a1, uint32_t a2, uint32_t a3,
                                         uint32_t b0, uint32_t b1) {
    asm volatile("mma.sync.aligned.m16n8k8.row.col.f32.tf32.tf32.f32 "
                 "{%0,%1,%2,%3}, {%4,%5,%6,%7}, {%8,%9}, {%0,%1,%2,%3};"
                 : "+f"(d0), "+f"(d1), "+f"(d2), "+f"(d3)
                 : "r"(a0), "r"(a1), "r"(a2), "r"(a3), "r"(b0), "r"(b1));
}

// ---------------- edge-index dtype probe + decode (+cnt zero) ----------------
__global__ void k_probe(const int* __restrict__ buf) {
    __shared__ int ok;
    if (threadIdx.x == 0) ok = 1;
    __syncthreads();
    int i = threadIdx.x;                 // 512 threads, pairs 0..511
    int lo = buf[2 * i];
    int hi = buf[2 * i + 1];
    if (!(hi == 0 && lo >= 0 && lo < N_NODES)) atomicAnd(&ok, 0);
    __syncthreads();
    if (threadIdx.x == 0) g_is64 = ok;
}

__global__ void k_decode(const void* __restrict__ buf) {
    int e = blockIdx.x * blockDim.x + threadIdx.x;
    if (e < N_NODES) g_cnt[e] = 0;       // fused zero of the histogram
    if (e >= 2 * N_EDGES) return;
    int v;
    if (g_is64) v = (int)((const long long*)buf)[e];
    else        v = ((const int*)buf)[e];
    v = v < 0 ? 0 : (v >= N_NODES ? N_NODES - 1 : v);
    g_eidx[e] = v;
}

// ---------------- CSR construction ----------------
__global__ void k_hist() {
    int e = blockIdx.x * blockDim.x + threadIdx.x;
    if (e < N_EDGES) {
        int d = g_eidx[N_EDGES + e];
        atomicAdd(&g_cnt[d], 1);
    }
}

__global__ void k_scan() {
    const int T = 1024;
    const int CH = (N_NODES + T - 1) / T;
    int t = threadIdx.x;
    int beg = t * CH;
    int end = beg + CH; if (end > N_NODES) end = N_NODES;
    int s = 0;
    for (int i = beg; i < end; i++) s += g_cnt[i];

    __shared__ int ps[T];
    ps[t] = s;
    __syncthreads();
    for (int off = 1; off < T; off <<= 1) {
        int v = 0;
        if (t >= off) v = ps[t - off];
        __syncthreads();
        ps[t] += v;
        __syncthreads();
    }
    int run = ps[t] - s;
    for (int i = beg; i < end; i++) {
        g_rowptr[i] = run;
        g_cursor[i] = run;
        run += g_cnt[i];
    }
    if (t == 0) g_rowptr[N_NODES] = N_EDGES;
}

__global__ void k_scatter() {
    int e = blockIdx.x * blockDim.x + threadIdx.x;
    if (e < N_EDGES) {
        int s = g_eidx[e];
        int d = g_eidx[N_EDGES + e];
        int pos = atomicAdd(&g_cursor[d], 1);
        g_perm[pos] = s;
    }
}

// ---------------- mean aggregation (layer 1): warp/node, 2-edge unroll for MLP ----------------
__global__ void __launch_bounds__(256) k_agg128(const float* __restrict__ feat,
                                                float* __restrict__ out) {
    int warp = (blockIdx.x * blockDim.x + threadIdx.x) >> 5;
    if (warp >= N_NODES) return;
    int lane = threadIdx.x & 31;

    int beg = g_rowptr[warp];
    int end = g_rowptr[warp + 1];

    float4 a0 = make_float4(0.f, 0.f, 0.f, 0.f);
    float4 a1 = make_float4(0.f, 0.f, 0.f, 0.f);
    int e = beg;
    for (; e + 1 < end; e += 2) {
        int s0 = g_perm[e];
        int s1 = g_perm[e + 1];
        float4 r0 = ((const float4*)(feat + (size_t)s0 * 128))[lane];
        float4 r1 = ((const float4*)(feat + (size_t)s1 * 128))[lane];
        a0 = f4add(a0, r0);
        a1 = f4add(a1, r1);
    }
    if (e < end) {
        int s0 = g_perm[e];
        a0 = f4add(a0, ((const float4*)(feat + (size_t)s0 * 128))[lane]);
    }
    a0 = f4add(a0, a1);
    int deg = end - beg;
    float inv = 1.0f / (float)(deg > 0 ? deg : 1);
    ((float4*)(out + (size_t)warp * 128))[lane] = f4scale(a0, inv);
}

// ---------------- fused layer-2 aggregation + epilogue (dense thread mapping) ----------------
// thread idx -> (node, slot): out4[node][slot] = mean_agg(P4[src][slot]) + Q4[node][slot]
__global__ void __launch_bounds__(256) k_agg40_add(const float* __restrict__ P,
                                                   const float* __restrict__ Q,
                                                   float* __restrict__ out) {
    int idx = blockIdx.x * blockDim.x + threadIdx.x;
    if (idx >= N_NODES * 10) return;
    int node = idx / 10;
    int slot = idx - node * 10;

    int beg = g_rowptr[node];
    int end = g_rowptr[node + 1];

    float4 a = make_float4(0.f, 0.f, 0.f, 0.f);
    float4 b = make_float4(0.f, 0.f, 0.f, 0.f);
    int e = beg;
    for (; e + 1 < end; e += 2) {
        int s0 = g_perm[e];
        int s1 = g_perm[e + 1];
        a = f4add(a, ((const float4*)(P + (size_t)s0 * 40))[slot]);
        b = f4add(b, ((const float4*)(P + (size_t)s1 * 40))[slot]);
    }
    if (e < end) {
        int s0 = g_perm[e];
        a = f4add(a, ((const float4*)(P + (size_t)s0 * 40))[slot]);
    }
    a = f4add(a, b);
    int deg = end - beg;
    float inv = 1.0f / (float)(deg > 0 ? deg : 1);
    float4 q = ((const float4*)(Q + (size_t)node * 40))[slot];
    ((float4*)(out + (size_t)node * 40))[slot] = f4add(f4scale(a, inv), q);
}

// ---------------- layer-1 GEMM on tensor cores (TF32 mma.sync, pipelined) ----------------
// h = relu( [Aagg | Ax] @ [W1l ; W1r] + b1 )   as one K=256 GEMM.
// BM=128, BN=128, BK=32; 8 warps 2(M)x4(N), warp tile 64x32 (4x4 m16n8k8).
// Register-prefetch pipeline hides global loads behind MMA compute.
__global__ void __launch_bounds__(256, 2) k_gemm1_tc(const float* __restrict__ Aagg,
                                                     const float* __restrict__ Ax,
                                                     const float* __restrict__ Wl,
                                                     const float* __restrict__ Wr,
                                                     const float* __restrict__ bias,
                                                     float* __restrict__ C) {
    __shared__ float sA[128][36];    // bank(frag) = 4*lr+lq  -> conflict-free
    __shared__ float sW[32][136];    // bank(frag) = 8*lq+lr  -> conflict-free

    int tid = threadIdx.x;
    int lane = tid & 31, wid = tid >> 5;
    int wm = wid & 1, wn = wid >> 1;         // 2(M) x 4(N)
    int mBase = blockIdx.x * 128;
    int nBase = blockIdx.y * 128;
    int lr = lane >> 2, lq = lane & 3;

    // loader coords
    int aRow = tid >> 3, aC4 = tid & 7;      // A: rows aRow + 32*rr, cols 4*aC4
    int wRow = tid >> 5, wC4 = tid & 31;     // W: rows wRow + 8*i, cols 4*wC4

    float d[4][4][4];
    #pragma unroll
    for (int mt = 0; mt < 4; mt++)
        #pragma unroll
        for (int nt = 0; nt < 4; nt++)
            #pragma unroll
            for (int j = 0; j < 4; j++) d[mt][nt][j] = 0.f;

    float4 pa[4], pw[4];

    // prologue: load tile kb=0
    {
        const float* Asrc = Aagg;
        const float* Wsrc = Wl;
        #pragma unroll
        for (int rr = 0; rr < 4; rr++) {
            int m = mBase + rr * 32 + aRow;
            pa[rr] = make_float4(0.f, 0.f, 0.f, 0.f);
            if (m < N_NODES) pa[rr] = *(const float4*)(Asrc + (size_t)m * 128 + aC4 * 4);
        }
        #pragma unroll
        for (int i = 0; i < 4; i++)
            pw[i] = *(const float4*)(Wsrc + (size_t)(wRow + 8 * i) * 256 + nBase + wC4 * 4);
    }
    #pragma unroll
    for (int rr = 0; rr < 4; rr++) *(float4*)&sA[rr * 32 + aRow][aC4 * 4] = cvt4_tf32(pa[rr]);
    #pragma unroll
    for (int i = 0; i < 4; i++)  *(float4*)&sW[wRow + 8 * i][wC4 * 4] = cvt4_tf32(pw[i]);
    __syncthreads();

    for (int kb8 = 0; kb8 < 8; kb8++) {
        // prefetch next tile into registers (overlaps with MMAs below)
        if (kb8 < 7) {
            int kb = (kb8 + 1) * 32;
            const float* Asrc = (kb < 128) ? Aagg : Ax;
            const float* Wsrc = (kb < 128) ? Wl : Wr;
            int kc = kb & 127;
            #pragma unroll
            for (int rr = 0; rr < 4; rr++) {
                int m = mBase + rr * 32 + aRow;
                pa[rr] = make_float4(0.f, 0.f, 0.f, 0.f);
                if (m < N_NODES) pa[rr] = *(const float4*)(Asrc + (size_t)m * 128 + kc + aC4 * 4);
            }
            #pragma unroll
            for (int i = 0; i < 4; i++)
                pw[i] = *(const float4*)(Wsrc + (size_t)(kc + wRow + 8 * i) * 256 + nBase + wC4 * 4);
        }

        // compute 4 k8 steps
        #pragma unroll
        for (int k8 = 0; k8 < 4; k8++) {
            int k0 = k8 * 8;
            uint32_t af[4][4], bf[4][2];
            #pragma unroll
            for (int mt = 0; mt < 4; mt++) {
                int rb = wm * 64 + mt * 16;
                af[mt][0] = __float_as_uint(sA[rb + lr][k0 + lq]);
                af[mt][1] = __float_as_uint(sA[rb + 8 + lr][k0 + lq]);
                af[mt][2] = __float_as_uint(sA[rb + lr][k0 + 4 + lq]);
                af[mt][3] = __float_as_uint(sA[rb + 8 + lr][k0 + 4 + lq]);
            }
            #pragma unroll
            for (int nt = 0; nt < 4; nt++) {
                int cb = wn * 32 + nt * 8;
                bf[nt][0] = __float_as_uint(sW[k0 + lq][cb + lr]);
                bf[nt][1] = __float_as_uint(sW[k0 + 4 + lq][cb + lr]);
            }
            #pragma unroll
            for (int mt = 0; mt < 4; mt++)
                #pragma unroll
                for (int nt = 0; nt < 4; nt++)
                    mma_tf32(d[mt][nt][0], d[mt][nt][1], d[mt][nt][2], d[mt][nt][3],
                             af[mt][0], af[mt][1], af[mt][2], af[mt][3],
                             bf[nt][0], bf[nt][1]);
        }
        __syncthreads();

        if (kb8 < 7) {
            #pragma unroll
            for (int rr = 0; rr < 4; rr++) *(float4*)&sA[rr * 32 + aRow][aC4 * 4] = cvt4_tf32(pa[rr]);
            #pragma unroll
            for (int i = 0; i < 4; i++)  *(float4*)&sW[wRow + 8 * i][wC4 * 4] = cvt4_tf32(pw[i]);
            __syncthreads();
        }
    }

    // epilogue: bias + relu, float2 stores
    #pragma unroll
    for (int mt = 0; mt < 4; mt++) {
        int rb = mBase + wm * 64 + mt * 16 + lr;
        #pragma unroll
        for (int nt = 0; nt < 4; nt++) {
            int c = nBase + wn * 32 + nt * 8 + lq * 2;
            float b0 = bias[c], b1 = bias[c + 1];
            if (rb < N_NODES) {
                float2 o;
                o.x = fmaxf(d[mt][nt][0] + b0, 0.f);
                o.y = fmaxf(d[mt][nt][1] + b1, 0.f);
                *(float2*)(C + (size_t)rb * 256 + c) = o;
            }
            if (rb + 8 < N_NODES) {
                float2 o;
                o.x = fmaxf(d[mt][nt][2] + b0, 0.f);
                o.y = fmaxf(d[mt][nt][3] + b1, 0.f);
                *(float2*)(C + (size_t)(rb + 8) * 256 + c) = o;
            }
        }
    }
}

// ---------------- layer-2 dual GEMM on tensor cores (TF32 mma.sync) ----------------
// P = h @ W2l,  Q = h @ W2r + b2   as one K=256, N=80 GEMM (W2l || W2r).
__global__ void __launch_bounds__(256) k_gemm2_tc(const float* __restrict__ A,
                                                  const float* __restrict__ Wl,
                                                  const float* __restrict__ Wr,
                                                  const float* __restrict__ bias,
                                                  float* __restrict__ P,
                                                  float* __restrict__ Q) {
    constexpr int BM = 128, BK = 32;
    __shared__ float sA[BM][36];
    __shared__ float sW[BK][88];

    int tid = threadIdx.x;
    int lane = tid & 31, wid = tid >> 5;
    int wm = wid >> 1, wn = wid & 1;
    int mBase = blockIdx.x * BM;
    int lr = lane >> 2, lq = lane & 3;

    float d[2][5][4];
    #pragma unroll
    for (int mt = 0; mt < 2; mt++)
        #pragma unroll
        for (int nt = 0; nt < 5; nt++)
            #pragma unroll
            for (int j = 0; j < 4; j++) d[mt][nt][j] = 0.f;

    for (int kb = 0; kb < 256; kb += BK) {
        #pragma unroll
        for (int rr = 0; rr < 4; rr++) {
            int row = rr * 32 + (tid >> 3);
            int c4  = tid & 7;
            int m   = mBase + row;
            float4 v = make_float4(0.f, 0.f, 0.f, 0.f);
            if (m < N_NODES) v = *(const float4*)(A + (size_t)m * 256 + kb + c4 * 4);
            *(float4*)&sA[row][c4 * 4] = cvt4_tf32(v);
        }
        for (int idx = tid; idx < 320; idx += 256) {
            int kk = idx / 10, c4 = idx % 10;
            float4 v = *(const float4*)(Wl + (size_t)(kb + kk) * 40 + c4 * 4);
            *(float4*)&sW[kk][c4 * 4] = cvt4_tf32(v);
        }
        for (int idx = tid; idx < 320; idx += 256) {
            int kk = idx / 10, c4 = idx % 10;
            float4 v = *(const float4*)(Wr + (size_t)(kb + kk) * 40 + c4 * 4);
            *(float4*)&sW[kk][40 + c4 * 4] = cvt4_tf32(v);
        }
        __syncthreads();

        #pragma unroll
        for (int k8 = 0; k8 < 4; k8++) {
            int k0 = k8 * 8;
            uint32_t af[2][4], bf[5][2];
            #pragma unroll
            for (int mt = 0; mt < 2; mt++) {
                int rb = wm * 32 + mt * 16;
                af[mt][0] = __float_as_uint(sA[rb + lr][k0 + lq]);
                af[mt][1] = __float_as_uint(sA[rb + 8 + lr][k0 + lq]);
                af[mt][2] = __float_as_uint(sA[rb + lr][k0 + 4 + lq]);
                af[mt][3] = __float_as_uint(sA[rb + 8 + lr][k0 + 4 + lq]);
            }
            #pragma unroll
            for (int nt = 0; nt < 5; nt++) {
                int cb = wn * 40 + nt * 8;
                bf[nt][0] = __float_as_uint(sW[k0 + lq][cb + lr]);
                bf[nt][1] = __float_as_uint(sW[k0 + 4 + lq][cb + lr]);
            }
            #pragma unroll
            for (int mt = 0; mt < 2; mt++)
                #pragma unroll
                for (int nt = 0; nt < 5; nt++)
                    mma_tf32(d[mt][nt][0], d[mt][nt][1], d[mt][nt][2], d[mt][nt][3],
                             af[mt][0], af[mt][1], af[mt][2], af[mt][3],
                             bf[nt][0], bf[nt][1]);
        }
        __syncthreads();
    }

    float* dst = wn ? Q : P;
    #pragma unroll
    for (int mt = 0; mt < 2; mt++) {
        int rb = mBase + wm * 32 + mt * 16 + lr;
        #pragma unroll
        for (int nt = 0; nt < 5; nt++) {
            int cc = nt * 8 + lq * 2;
            float b0 = wn ? bias[cc] : 0.f;
            float b1 = wn ? bias[cc + 1] : 0.f;
            if (rb < N_NODES) {
                float2 o = make_float2(d[mt][nt][0] + b0, d[mt][nt][1] + b1);
                *(float2*)(dst + (size_t)rb * 40 + cc) = o;
            }
            if (rb + 8 < N_NODES) {
                float2 o = make_float2(d[mt][nt][2] + b0, d[mt][nt][3] + b1);
                *(float2*)(dst + (size_t)(rb + 8) * 40 + cc) = o;
            }
        }
    }
}

// ---------------- launch ----------------
extern "C" void kernel_launch(void* const* d_in, const int* in_sizes, int n_in,
                              void* d_out, int out_size) {
    const float* x   = (const float*)d_in[0];
    const void*  ei  = d_in[1];                  // int32 or int64 — probed on device
    const float* W1l = (const float*)d_in[2];
    const float* b1  = (const float*)d_in[3];
    const float* W1r = (const float*)d_in[4];
    const float* W2l = (const float*)d_in[5];
    const float* b2  = (const float*)d_in[6];
    const float* W2r = (const float*)d_in[7];
    float* out = (float*)d_out;

    float *agg = nullptr, *h = nullptr, *P = nullptr, *Q = nullptr;
    cudaGetSymbolAddress((void**)&agg, g_agg);
    cudaGetSymbolAddress((void**)&h, g_h);
    cudaGetSymbolAddress((void**)&P, g_P);
    cudaGetSymbolAddress((void**)&Q, g_Q);

    const int TB = 256;

    // edge-index decode (dtype-agnostic) + cnt zero
    k_probe<<<1, 512>>>((const int*)ei);
    k_decode<<<(2 * N_EDGES + TB - 1) / TB, TB>>>(ei);

    // CSR build
    k_hist<<<(N_EDGES + TB - 1) / TB, TB>>>();
    k_scan<<<1, 1024>>>();
    k_scatter<<<(N_EDGES + TB - 1) / TB, TB>>>();

    int aggBlocks = (N_NODES * 32 + TB - 1) / TB;

    // layer 1: agg(x) -> TF32 tensor-core GEMM (BN=128, pipelined) -> h
    k_agg128<<<aggBlocks, TB>>>(x, agg);
    dim3 g1((N_NODES + 127) / 128, HID_DIM / 128);
    k_gemm1_tc<<<g1, 256>>>(agg, x, W1l, W1r, b1, h);

    // layer 2 (aggregation commuted past the projection):
    //   P = h@W2l, Q = h@W2r + b2;  out = mean_agg(P) + Q
    k_gemm2_tc<<<(N_NODES + 127) / 128, 256>>>(h, W2l, W2r, b2, P, Q);
    k_agg40_add<<<(N_NODES * 10 + TB - 1) / TB, TB>>>(P, Q, out);
}

// round 17
// speedup vs baseline: 6.3327x; 1.5876x over previous
#include <cuda_runtime.h>
#include <cstdint>

#define N_NODES 100000
#define N_EDGES 800000
#define IN_DIM 128
#define HID_DIM 256
#define OUT_DIM 40
#define SCAN_NB ((N_NODES + 1023) / 1024)   // 98 scan blocks

// ---------------- scratch (device globals; no allocation allowed) ----------------
__device__ int   g_is64;
__device__ int   g_eidx[2 * N_EDGES];            // decoded edge index (src | dst)
__device__ int   g_cnt[N_NODES];
__device__ int   g_rowptr[N_NODES + 1];
__device__ int   g_cursor[N_NODES];
__device__ int   g_perm[N_EDGES];
__device__ int   g_bsum[128];                    // scan block totals
__device__ int   g_boff[128];                    // scan block exclusive offsets
__device__ float g_agg[(size_t)N_NODES * 128];   // layer-1 mean aggregate
__device__ float g_h[(size_t)N_NODES * 256];     // hidden layer
__device__ float g_P[(size_t)N_NODES * 40];      // h @ W2l   (pre-aggregation)
__device__ float g_Q[(size_t)N_NODES * 40];      // h @ W2r + b2

// ---------------- small helpers ----------------
__device__ __forceinline__ float4 f4add(float4 a, float4 b) {
    a.x += b.x; a.y += b.y; a.z += b.z; a.w += b.w; return a;
}
__device__ __forceinline__ float4 f4scale(float4 a, float s) {
    a.x *= s; a.y *= s; a.z *= s; a.w *= s; return a;
}
__device__ __forceinline__ float cvt_tf32(float x) {
    float y;
    asm("cvt.rna.tf32.f32 %0, %1;" : "=f"(y) : "f"(x));
    return y;
}
__device__ __forceinline__ float4 cvt4_tf32(float4 v) {
    v.x = cvt_tf32(v.x); v.y = cvt_tf32(v.y);
    v.z = cvt_tf32(v.z); v.w = cvt_tf32(v.w);
    return v;
}
__device__ __forceinline__ void mma_tf32(float& d0, float& d1, float& d2, float& d3,
                                         uint32_t a0, uint32_t a1, uint32_t a2, uint32_t a3,
                                         uint32_t b0, uint32_t b1) {
    asm volatile("mma.sync.aligned.m16n8k8.row.col.f32.tf32.tf32.f32 "
                 "{%0,%1,%2,%3}, {%4,%5,%6,%7}, {%8,%9}, {%0,%1,%2,%3};"
                 : "+f"(d0), "+f"(d1), "+f"(d2), "+f"(d3)
                 : "r"(a0), "r"(a1), "r"(a2), "r"(a3), "r"(b0), "r"(b1));
}

// ---------------- edge-index dtype probe + decode (+cnt zero) ----------------
__global__ void k_probe(const int* __restrict__ buf) {
    __shared__ int ok;
    if (threadIdx.x == 0) ok = 1;
    __syncthreads();
    int i = threadIdx.x;                 // 512 threads, pairs 0..511
    int lo = buf[2 * i];
    int hi = buf[2 * i + 1];
    if (!(hi == 0 && lo >= 0 && lo < N_NODES)) atomicAnd(&ok, 0);
    __syncthreads();
    if (threadIdx.x == 0) g_is64 = ok;
}

__global__ void k_decode(const void* __restrict__ buf) {
    int e = blockIdx.x * blockDim.x + threadIdx.x;
    if (e < N_NODES) g_cnt[e] = 0;       // fused zero of the histogram
    if (e >= 2 * N_EDGES) return;
    int v;
    if (g_is64) v = (int)((const long long*)buf)[e];
    else        v = ((const int*)buf)[e];
    v = v < 0 ? 0 : (v >= N_NODES ? N_NODES - 1 : v);
    g_eidx[e] = v;
}

// ---------------- CSR construction ----------------
__global__ void k_hist() {
    int e = blockIdx.x * blockDim.x + threadIdx.x;
    if (e < N_EDGES) {
        int d = g_eidx[N_EDGES + e];
        atomicAdd(&g_cnt[d], 1);
    }
}

// phase A: per-block inclusive scan of 1024 counts; inclusive -> g_rowptr (temp),
// block total -> g_bsum
__global__ void __launch_bounds__(1024) k_scanA() {
    __shared__ int sh[1024];
    int t = threadIdx.x;
    int i = blockIdx.x * 1024 + t;
    int v = (i < N_NODES) ? g_cnt[i] : 0;
    sh[t] = v;
    __syncthreads();
    #pragma unroll
    for (int off = 1; off < 1024; off <<= 1) {
        int u = (t >= off) ? sh[t - off] : 0;
        __syncthreads();
        sh[t] += u;
        __syncthreads();
    }
    if (i < N_NODES) g_rowptr[i] = sh[t];          // inclusive (temp)
    if (t == 1023) g_bsum[blockIdx.x] = sh[1023];
}

// phase B: scan the block totals (SCAN_NB <= 128) -> exclusive offsets
__global__ void k_scanB() {
    __shared__ int sh[128];
    int t = threadIdx.x;
    int v = (t < SCAN_NB) ? g_bsum[t] : 0;
    sh[t] = v;
    __syncthreads();
    #pragma unroll
    for (int off = 1; off < 128; off <<= 1) {
        int u = (t >= off) ? sh[t - off] : 0;
        __syncthreads();
        sh[t] += u;
        __syncthreads();
    }
    if (t < SCAN_NB) g_boff[t] = sh[t] - v;        // exclusive
}

// phase C: finalize exclusive rowptr + cursor
__global__ void k_scanC() {
    int i = blockIdx.x * blockDim.x + threadIdx.x;
    if (i > N_NODES) return;
    if (i == N_NODES) { g_rowptr[N_NODES] = N_EDGES; return; }
    int excl = g_boff[i >> 10] + g_rowptr[i] - g_cnt[i];
    g_rowptr[i] = excl;
    g_cursor[i] = excl;
}

__global__ void k_scatter() {
    int e = blockIdx.x * blockDim.x + threadIdx.x;
    if (e < N_EDGES) {
        int s = g_eidx[e];
        int d = g_eidx[N_EDGES + e];
        int pos = atomicAdd(&g_cursor[d], 1);
        g_perm[pos] = s;
    }
}

// ---------------- mean aggregation (layer 1): warp/node, 2-edge unroll for MLP ----------------
__global__ void __launch_bounds__(256) k_agg128(const float* __restrict__ feat,
                                                float* __restrict__ out) {
    int warp = (blockIdx.x * blockDim.x + threadIdx.x) >> 5;
    if (warp >= N_NODES) return;
    int lane = threadIdx.x & 31;

    int beg = g_rowptr[warp];
    int end = g_rowptr[warp + 1];

    float4 a0 = make_float4(0.f, 0.f, 0.f, 0.f);
    float4 a1 = make_float4(0.f, 0.f, 0.f, 0.f);
    int e = beg;
    for (; e + 1 < end; e += 2) {
        int s0 = g_perm[e];
        int s1 = g_perm[e + 1];
        float4 r0 = ((const float4*)(feat + (size_t)s0 * 128))[lane];
        float4 r1 = ((const float4*)(feat + (size_t)s1 * 128))[lane];
        a0 = f4add(a0, r0);
        a1 = f4add(a1, r1);
    }
    if (e < end) {
        int s0 = g_perm[e];
        a0 = f4add(a0, ((const float4*)(feat + (size_t)s0 * 128))[lane]);
    }
    a0 = f4add(a0, a1);
    int deg = end - beg;
    float inv = 1.0f / (float)(deg > 0 ? deg : 1);
    ((float4*)(out + (size_t)warp * 128))[lane] = f4scale(a0, inv);
}

// ---------------- fused layer-2 aggregation + epilogue (dense thread mapping) ----------------
__global__ void __launch_bounds__(256) k_agg40_add(const float* __restrict__ P,
                                                   const float* __restrict__ Q,
                                                   float* __restrict__ out) {
    int idx = blockIdx.x * blockDim.x + threadIdx.x;
    if (idx >= N_NODES * 10) return;
    int node = idx / 10;
    int slot = idx - node * 10;

    int beg = g_rowptr[node];
    int end = g_rowptr[node + 1];

    float4 a = make_float4(0.f, 0.f, 0.f, 0.f);
    float4 b = make_float4(0.f, 0.f, 0.f, 0.f);
    int e = beg;
    for (; e + 1 < end; e += 2) {
        int s0 = g_perm[e];
        int s1 = g_perm[e + 1];
        a = f4add(a, ((const float4*)(P + (size_t)s0 * 40))[slot]);
        b = f4add(b, ((const float4*)(P + (size_t)s1 * 40))[slot]);
    }
    if (e < end) {
        int s0 = g_perm[e];
        a = f4add(a, ((const float4*)(P + (size_t)s0 * 40))[slot]);
    }
    a = f4add(a, b);
    int deg = end - beg;
    float inv = 1.0f / (float)(deg > 0 ? deg : 1);
    float4 q = ((const float4*)(Q + (size_t)node * 40))[slot];
    ((float4*)(out + (size_t)node * 40))[slot] = f4add(f4scale(a, inv), q);
}

// ---------------- layer-1 GEMM on tensor cores (TF32 mma.sync, pipelined) ----------------
__global__ void __launch_bounds__(256, 2) k_gemm1_tc(const float* __restrict__ Aagg,
                                                     const float* __restrict__ Ax,
                                                     const float* __restrict__ Wl,
                                                     const float* __restrict__ Wr,
                                                     const float* __restrict__ bias,
                                                     float* __restrict__ C) {
    __shared__ float sA[128][36];    // bank(frag) = 4*lr+lq  -> conflict-free
    __shared__ float sW[32][136];    // bank(frag) = 8*lq+lr  -> conflict-free

    int tid = threadIdx.x;
    int lane = tid & 31, wid = tid >> 5;
    int wm = wid & 1, wn = wid >> 1;         // 2(M) x 4(N)
    int mBase = blockIdx.x * 128;
    int nBase = blockIdx.y * 128;
    int lr = lane >> 2, lq = lane & 3;

    int aRow = tid >> 3, aC4 = tid & 7;
    int wRow = tid >> 5, wC4 = tid & 31;

    float d[4][4][4];
    #pragma unroll
    for (int mt = 0; mt < 4; mt++)
        #pragma unroll
        for (int nt = 0; nt < 4; nt++)
            #pragma unroll
            for (int j = 0; j < 4; j++) d[mt][nt][j] = 0.f;

    float4 pa[4], pw[4];

    {
        const float* Asrc = Aagg;
        const float* Wsrc = Wl;
        #pragma unroll
        for (int rr = 0; rr < 4; rr++) {
            int m = mBase + rr * 32 + aRow;
            pa[rr] = make_float4(0.f, 0.f, 0.f, 0.f);
            if (m < N_NODES) pa[rr] = *(const float4*)(Asrc + (size_t)m * 128 + aC4 * 4);
        }
        #pragma unroll
        for (int i = 0; i < 4; i++)
            pw[i] = *(const float4*)(Wsrc + (size_t)(wRow + 8 * i) * 256 + nBase + wC4 * 4);
    }
    #pragma unroll
    for (int rr = 0; rr < 4; rr++) *(float4*)&sA[rr * 32 + aRow][aC4 * 4] = cvt4_tf32(pa[rr]);
    #pragma unroll
    for (int i = 0; i < 4; i++)  *(float4*)&sW[wRow + 8 * i][wC4 * 4] = cvt4_tf32(pw[i]);
    __syncthreads();

    for (int kb8 = 0; kb8 < 8; kb8++) {
        if (kb8 < 7) {
            int kb = (kb8 + 1) * 32;
            const float* Asrc = (kb < 128) ? Aagg : Ax;
            const float* Wsrc = (kb < 128) ? Wl : Wr;
            int kc = kb & 127;
            #pragma unroll
            for (int rr = 0; rr < 4; rr++) {
                int m = mBase + rr * 32 + aRow;
                pa[rr] = make_float4(0.f, 0.f, 0.f, 0.f);
                if (m < N_NODES) pa[rr] = *(const float4*)(Asrc + (size_t)m * 128 + kc + aC4 * 4);
            }
            #pragma unroll
            for (int i = 0; i < 4; i++)
                pw[i] = *(const float4*)(Wsrc + (size_t)(kc + wRow + 8 * i) * 256 + nBase + wC4 * 4);
        }

        #pragma unroll
        for (int k8 = 0; k8 < 4; k8++) {
            int k0 = k8 * 8;
            uint32_t af[4][4], bf[4][2];
            #pragma unroll
            for (int mt = 0; mt < 4; mt++) {
                int rb = wm * 64 + mt * 16;
                af[mt][0] = __float_as_uint(sA[rb + lr][k0 + lq]);
                af[mt][1] = __float_as_uint(sA[rb + 8 + lr][k0 + lq]);
                af[mt][2] = __float_as_uint(sA[rb + lr][k0 + 4 + lq]);
                af[mt][3] = __float_as_uint(sA[rb + 8 + lr][k0 + 4 + lq]);
            }
            #pragma unroll
            for (int nt = 0; nt < 4; nt++) {
                int cb = wn * 32 + nt * 8;
                bf[nt][0] = __float_as_uint(sW[k0 + lq][cb + lr]);
                bf[nt][1] = __float_as_uint(sW[k0 + 4 + lq][cb + lr]);
            }
            #pragma unroll
            for (int mt = 0; mt < 4; mt++)
                #pragma unroll
                for (int nt = 0; nt < 4; nt++)
                    mma_tf32(d[mt][nt][0], d[mt][nt][1], d[mt][nt][2], d[mt][nt][3],
                             af[mt][0], af[mt][1], af[mt][2], af[mt][3],
                             bf[nt][0], bf[nt][1]);
        }
        __syncthreads();

        if (kb8 < 7) {
            #pragma unroll
            for (int rr = 0; rr < 4; rr++) *(float4*)&sA[rr * 32 + aRow][aC4 * 4] = cvt4_tf32(pa[rr]);
            #pragma unroll
            for (int i = 0; i < 4; i++)  *(float4*)&sW[wRow + 8 * i][wC4 * 4] = cvt4_tf32(pw[i]);
            __syncthreads();
        }
    }

    #pragma unroll
    for (int mt = 0; mt < 4; mt++) {
        int rb = mBase + wm * 64 + mt * 16 + lr;
        #pragma unroll
        for (int nt = 0; nt < 4; nt++) {
            int c = nBase + wn * 32 + nt * 8 + lq * 2;
            float b0 = bias[c], b1 = bias[c + 1];
            if (rb < N_NODES) {
                float2 o;
                o.x = fmaxf(d[mt][nt][0] + b0, 0.f);
                o.y = fmaxf(d[mt][nt][1] + b1, 0.f);
                *(float2*)(C + (size_t)rb * 256 + c) = o;
            }
            if (rb + 8 < N_NODES) {
                float2 o;
                o.x = fmaxf(d[mt][nt][2] + b0, 0.f);
                o.y = fmaxf(d[mt][nt][3] + b1, 0.f);
                *(float2*)(C + (size_t)(rb + 8) * 256 + c) = o;
            }
        }
    }
}

// ---------------- layer-2 dual GEMM on tensor cores (TF32 mma.sync) ----------------
__global__ void __launch_bounds__(256) k_gemm2_tc(const float* __restrict__ A,
                                                  const float* __restrict__ Wl,
                                                  const float* __restrict__ Wr,
                                                  const float* __restrict__ bias,
                                                  float* __restrict__ P,
                                                  float* __restrict__ Q) {
    constexpr int BM = 128, BK = 32;
    __shared__ float sA[BM][36];
    __shared__ float sW[BK][88];

    int tid = threadIdx.x;
    int lane = tid & 31, wid = tid >> 5;
    int wm = wid >> 1, wn = wid & 1;
    int mBase = blockIdx.x * BM;
    int lr = lane >> 2, lq = lane & 3;

    float d[2][5][4];
    #pragma unroll
    for (int mt = 0; mt < 2; mt++)
        #pragma unroll
        for (int nt = 0; nt < 5; nt++)
            #pragma unroll
            for (int j = 0; j < 4; j++) d[mt][nt][j] = 0.f;

    for (int kb = 0; kb < 256; kb += BK) {
        #pragma unroll
        for (int rr = 0; rr < 4; rr++) {
            int row = rr * 32 + (tid >> 3);
            int c4  = tid & 7;
            int m   = mBase + row;
            float4 v = make_float4(0.f, 0.f, 0.f, 0.f);
            if (m < N_NODES) v = *(const float4*)(A + (size_t)m * 256 + kb + c4 * 4);
            *(float4*)&sA[row][c4 * 4] = cvt4_tf32(v);
        }
        for (int idx = tid; idx < 320; idx += 256) {
            int kk = idx / 10, c4 = idx % 10;
            float4 v = *(const float4*)(Wl + (size_t)(kb + kk) * 40 + c4 * 4);
            *(float4*)&sW[kk][c4 * 4] = cvt4_tf32(v);
        }
        for (int idx = tid; idx < 320; idx += 256) {
            int kk = idx / 10, c4 = idx % 10;
            float4 v = *(const float4*)(Wr + (size_t)(kb + kk) * 40 + c4 * 4);
            *(float4*)&sW[kk][40 + c4 * 4] = cvt4_tf32(v);
        }
        __syncthreads();

        #pragma unroll
        for (int k8 = 0; k8 < 4; k8++) {
            int k0 = k8 * 8;
            uint32_t af[2][4], bf[5][2];
            #pragma unroll
            for (int mt = 0; mt < 2; mt++) {
                int rb = wm * 32 + mt * 16;
                af[mt][0] = __float_as_uint(sA[rb + lr][k0 + lq]);
                af[mt][1] = __float_as_uint(sA[rb + 8 + lr][k0 + lq]);
                af[mt][2] = __float_as_uint(sA[rb + lr][k0 + 4 + lq]);
                af[mt][3] = __float_as_uint(sA[rb + 8 + lr][k0 + 4 + lq]);
            }
            #pragma unroll
            for (int nt = 0; nt < 5; nt++) {
                int cb = wn * 40 + nt * 8;
                bf[nt][0] = __float_as_uint(sW[k0 + lq][cb + lr]);
                bf[nt][1] = __float_as_uint(sW[k0 + 4 + lq][cb + lr]);
            }
            #pragma unroll
            for (int mt = 0; mt < 2; mt++)
                #pragma unroll
                for (int nt = 0; nt < 5; nt++)
                    mma_tf32(d[mt][nt][0], d[mt][nt][1], d[mt][nt][2], d[mt][nt][3],
                             af[mt][0], af[mt][1], af[mt][2], af[mt][3],
                             bf[nt][0], bf[nt][1]);
        }
        __syncthreads();
    }

    float* dst = wn ? Q : P;
    #pragma unroll
    for (int mt = 0; mt < 2; mt++) {
        int rb = mBase + wm * 32 + mt * 16 + lr;
        #pragma unroll
        for (int nt = 0; nt < 5; nt++) {
            int cc = nt * 8 + lq * 2;
            float b0 = wn ? bias[cc] : 0.f;
            float b1 = wn ? bias[cc + 1] : 0.f;
            if (rb < N_NODES) {
                float2 o = make_float2(d[mt][nt][0] + b0, d[mt][nt][1] + b1);
                *(float2*)(dst + (size_t)rb * 40 + cc) = o;
            }
            if (rb + 8 < N_NODES) {
                float2 o = make_float2(d[mt][nt][2] + b0, d[mt][nt][3] + b1);
                *(float2*)(dst + (size_t)(rb + 8) * 40 + cc) = o;
            }
        }
    }
}

// ---------------- launch ----------------
extern "C" void kernel_launch(void* const* d_in, const int* in_sizes, int n_in,
                              void* d_out, int out_size) {
    const float* x   = (const float*)d_in[0];
    const void*  ei  = d_in[1];                  // int32 or int64 — probed on device
    const float* W1l = (const float*)d_in[2];
    const float* b1  = (const float*)d_in[3];
    const float* W1r = (const float*)d_in[4];
    const float* W2l = (const float*)d_in[5];
    const float* b2  = (const float*)d_in[6];
    const float* W2r = (const float*)d_in[7];
    float* out = (float*)d_out;

    float *agg = nullptr, *h = nullptr, *P = nullptr, *Q = nullptr;
    cudaGetSymbolAddress((void**)&agg, g_agg);
    cudaGetSymbolAddress((void**)&h, g_h);
    cudaGetSymbolAddress((void**)&P, g_P);
    cudaGetSymbolAddress((void**)&Q, g_Q);

    const int TB = 256;

    // edge-index decode (dtype-agnostic) + cnt zero
    k_probe<<<1, 512>>>((const int*)ei);
    k_decode<<<(2 * N_EDGES + TB - 1) / TB, TB>>>(ei);

    // CSR build (parallel 3-phase scan)
    k_hist<<<(N_EDGES + TB - 1) / TB, TB>>>();
    k_scanA<<<SCAN_NB, 1024>>>();
    k_scanB<<<1, 128>>>();
    k_scanC<<<(N_NODES + 1 + TB - 1) / TB, TB>>>();
    k_scatter<<<(N_EDGES + TB - 1) / TB, TB>>>();

    int aggBlocks = (N_NODES * 32 + TB - 1) / TB;

    // layer 1: agg(x) -> TF32 tensor-core GEMM (BN=128, pipelined) -> h
    k_agg128<<<aggBlocks, TB>>>(x, agg);
    dim3 g1((N_NODES + 127) / 128, HID_DIM / 128);
    k_gemm1_tc<<<g1, 256>>>(agg, x, W1l, W1r, b1, h);

    // layer 2 (aggregation commuted past the projection):
    //   P = h@W2l, Q = h@W2r + b2;  out = mean_agg(P) + Q
    k_gemm2_tc<<<(N_NODES + 127) / 128, 256>>>(h, W2l, W2r, b2, P, Q);
    k_agg40_add<<<(N_NODES * 10 + TB - 1) / TB, TB>>>(P, Q, out);
}